// round 1
// baseline (speedup 1.0000x reference)
#include <cuda_runtime.h>
#include <cuda_bf16.h>
#include <cstdio>

// ---------------------------------------------------------------------------
// Problem constants
// ---------------------------------------------------------------------------
#define TT   4096          // sequence length
#define HIDD 4096          // hidden dim
#define HH   32            // heads
#define DD   64            // head dim
#define PP   2048          // H*D
#define KC   4             // conv kernel

// ---------------------------------------------------------------------------
// Device scratch (allocation-free rule: use __device__ globals)
// ---------------------------------------------------------------------------
__device__ float d_xq[TT * PP];
__device__ float d_xk[TT * PP];
__device__ float d_xv[TT * PP];
__device__ float d_q [TT * PP];
__device__ float d_k [TT * PP];
__device__ float d_v [TT * PP];
__device__ float d_gl[TT * PP];   // g-lin then (in-place) exp(g) decay
__device__ float d_g2[TT * PP];   // output gate pre-sigmoid
__device__ float d_o [TT * PP];   // scan output, then gated-normed in place
__device__ float d_fa[TT * DD];
__device__ float d_ga[TT * DD];
__device__ float d_bl[TT * HH];   // beta pre-sigmoid

// ---------------------------------------------------------------------------
// Generic SIMT fp32 GEMM: C[M,N] = A[M,K] @ B[K,N], all row-major.
// Requires K % BK == 0, N % 4 == 0 (true for all shapes here). M,N guarded.
// ---------------------------------------------------------------------------
template <int BM, int BN, int BK, int TM, int TN>
__global__ void __launch_bounds__(256)
sgemm_kernel(const float* __restrict__ A, const float* __restrict__ B,
             float* __restrict__ C, int M, int N, int K)
{
    __shared__ float As[BK][BM + 4];
    __shared__ float Bs[BK][BN];

    const int tid = threadIdx.x;
    const int tx  = tid % (BN / TN);
    const int ty  = tid / (BN / TN);
    const int rowBase = blockIdx.y * BM;
    const int colBase = blockIdx.x * BN;

    float acc[TM][TN];
#pragma unroll
    for (int i = 0; i < TM; i++)
#pragma unroll
        for (int j = 0; j < TN; j++) acc[i][j] = 0.f;

    constexpr int A4 = BM * BK / 4;
    constexpr int B4 = BK * BN / 4;

    for (int kb = 0; kb < K; kb += BK) {
        // load A tile (transposed into As)
        for (int i = tid; i < A4; i += 256) {
            int r  = i / (BK / 4);
            int c4 = (i % (BK / 4)) * 4;
            float4 v = make_float4(0.f, 0.f, 0.f, 0.f);
            int gr = rowBase + r;
            if (gr < M)
                v = *reinterpret_cast<const float4*>(&A[(size_t)gr * K + kb + c4]);
            As[c4 + 0][r] = v.x; As[c4 + 1][r] = v.y;
            As[c4 + 2][r] = v.z; As[c4 + 3][r] = v.w;
        }
        // load B tile
        for (int i = tid; i < B4; i += 256) {
            int r  = i / (BN / 4);
            int c4 = (i % (BN / 4)) * 4;
            float4 v = make_float4(0.f, 0.f, 0.f, 0.f);
            int gc = colBase + c4;
            if (gc < N)
                v = *reinterpret_cast<const float4*>(&B[(size_t)(kb + r) * N + gc]);
            *reinterpret_cast<float4*>(&Bs[r][c4]) = v;
        }
        __syncthreads();

#pragma unroll
        for (int kk = 0; kk < BK; kk++) {
            float ra[TM], rb[TN];
#pragma unroll
            for (int i = 0; i < TM; i++) ra[i] = As[kk][ty * TM + i];
#pragma unroll
            for (int j = 0; j < TN; j++) rb[j] = Bs[kk][tx * TN + j];
#pragma unroll
            for (int i = 0; i < TM; i++)
#pragma unroll
                for (int j = 0; j < TN; j++)
                    acc[i][j] = fmaf(ra[i], rb[j], acc[i][j]);
        }
        __syncthreads();
    }

#pragma unroll
    for (int i = 0; i < TM; i++) {
        int r = rowBase + ty * TM + i;
        if (r >= M) continue;
#pragma unroll
        for (int j = 0; j < TN; j++) {
            int c = colBase + tx * TN + j;
            if (c < N) C[(size_t)r * N + c] = acc[i][j];
        }
    }
}

// ---------------------------------------------------------------------------
// Depthwise causal conv (K=4) + SiLU, optional per-(t,h) L2 norm.
// mode 0: conv+silu (v) ; mode 1: +l2norm (k) ; mode 2: +l2norm * D^-0.5 (q)
// grid (T, H/8), block 256 (8 warps, one (t,h) per warp, 2 d per lane)
// ---------------------------------------------------------------------------
__global__ void conv_silu_kernel(const float* __restrict__ x,
                                 const float* __restrict__ w,
                                 float* __restrict__ y, int mode)
{
    const int t    = blockIdx.x;
    const int h    = blockIdx.y * 8 + (threadIdx.x >> 5);
    const int lane = threadIdx.x & 31;

    float val[2];
    float ss = 0.f;
#pragma unroll
    for (int e = 0; e < 2; e++) {
        int d = lane + e * 32;
        int p = h * DD + d;
        const float* xp = x + p;
        float w0 = w[p * 4 + 0], w1 = w[p * 4 + 1];
        float w2 = w[p * 4 + 2], w3 = w[p * 4 + 3];
        float acc = xp[(size_t)t * PP] * w3;
        if (t >= 1) acc = fmaf(xp[(size_t)(t - 1) * PP], w2, acc);
        if (t >= 2) acc = fmaf(xp[(size_t)(t - 2) * PP], w1, acc);
        if (t >= 3) acc = fmaf(xp[(size_t)(t - 3) * PP], w0, acc);
        float sv = acc / (1.f + __expf(-acc));   // SiLU
        val[e] = sv;
        ss += sv * sv;
    }
    if (mode > 0) {
        ss += __shfl_xor_sync(0xffffffffu, ss, 16);
        ss += __shfl_xor_sync(0xffffffffu, ss, 8);
        ss += __shfl_xor_sync(0xffffffffu, ss, 4);
        ss += __shfl_xor_sync(0xffffffffu, ss, 2);
        ss += __shfl_xor_sync(0xffffffffu, ss, 1);
        float r = rsqrtf(ss + 1e-6f);
        if (mode == 2) r *= 0.125f;             // D^-0.5, D=64
        val[0] *= r; val[1] *= r;
    }
    size_t base = (size_t)t * PP + h * DD;
    y[base + lane]      = val[0];
    y[base + lane + 32] = val[1];
}

// ---------------------------------------------------------------------------
// Decay epilogue: gl <- exp( -exp(A_log[h]) * softplus(gl + dt_bias[p]) )
// ---------------------------------------------------------------------------
__global__ void decay_kernel(float* __restrict__ gl,
                             const float* __restrict__ dtb,
                             const float* __restrict__ Alog)
{
    const size_t total = (size_t)TT * PP;
    for (size_t idx = (size_t)blockIdx.x * blockDim.x + threadIdx.x;
         idx < total; idx += (size_t)gridDim.x * blockDim.x) {
        int pr = (int)(idx & (PP - 1));
        int h  = pr >> 6;
        float xv = gl[idx] + dtb[pr];
        float sp = (xv > 20.f) ? xv : log1pf(expf(xv));
        gl[idx] = expf(-expf(Alog[h]) * sp);
    }
}

// ---------------------------------------------------------------------------
// KDA sequential scan. One block per head (grid 32), 256 threads = 8 warps.
// Warp w owns columns [w*8, w*8+8); lane: quarter = lane>>3 -> k range 16,
// col = w*8 + (lane&7). No block-level syncs: each column lives in one warp.
// 2-step register prefetch + L2 prefetch 8 steps ahead hides memory latency.
// ---------------------------------------------------------------------------
__device__ __forceinline__ float kda_step(float S[16],
                                          const float eg[16], const float kk[16],
                                          const float qq[16], float vv, float braw)
{
    float vp0 = 0.f, vp1 = 0.f, vp2 = 0.f, vp3 = 0.f;
#pragma unroll
    for (int j = 0; j < 16; j += 4) {
        float s0 = S[j + 0] * eg[j + 0]; S[j + 0] = s0; vp0 = fmaf(kk[j + 0], s0, vp0);
        float s1 = S[j + 1] * eg[j + 1]; S[j + 1] = s1; vp1 = fmaf(kk[j + 1], s1, vp1);
        float s2 = S[j + 2] * eg[j + 2]; S[j + 2] = s2; vp2 = fmaf(kk[j + 2], s2, vp2);
        float s3 = S[j + 3] * eg[j + 3]; S[j + 3] = s3; vp3 = fmaf(kk[j + 3], s3, vp3);
    }
    float vpred = (vp0 + vp1) + (vp2 + vp3);
    vpred += __shfl_xor_sync(0xffffffffu, vpred, 8);
    vpred += __shfl_xor_sync(0xffffffffu, vpred, 16);
    float b = 1.f / (1.f + __expf(-braw));
    float delta = (vv - vpred) * b;
    float o0 = 0.f, o1 = 0.f, o2 = 0.f, o3 = 0.f;
#pragma unroll
    for (int j = 0; j < 16; j += 4) {
        S[j + 0] = fmaf(kk[j + 0], delta, S[j + 0]); o0 = fmaf(qq[j + 0], S[j + 0], o0);
        S[j + 1] = fmaf(kk[j + 1], delta, S[j + 1]); o1 = fmaf(qq[j + 1], S[j + 1], o1);
        S[j + 2] = fmaf(kk[j + 2], delta, S[j + 2]); o2 = fmaf(qq[j + 2], S[j + 2], o2);
        S[j + 3] = fmaf(kk[j + 3], delta, S[j + 3]); o3 = fmaf(qq[j + 3], S[j + 3], o3);
    }
    float ov = (o0 + o1) + (o2 + o3);
    ov += __shfl_xor_sync(0xffffffffu, ov, 8);
    ov += __shfl_xor_sync(0xffffffffu, ov, 16);
    return ov;
}

__global__ void __launch_bounds__(256, 1)
kda_scan_kernel(const float* __restrict__ qg, const float* __restrict__ kg,
                const float* __restrict__ vg, const float* __restrict__ egg,
                const float* __restrict__ bg, float* __restrict__ og)
{
    const int h       = blockIdx.x;
    const int warp    = threadIdx.x >> 5;
    const int lane    = threadIdx.x & 31;
    const int quarter = lane >> 3;
    const int col     = (warp << 3) + (lane & 7);
    const int kb      = quarter << 4;

    const float* ep  = egg + h * DD + kb;
    const float* kp  = kg  + h * DD + kb;
    const float* qp  = qg  + h * DD + kb;
    const float* vpt = vg  + h * DD + col;
    const float* bpt = bg  + h;

    float S[16];
#pragma unroll
    for (int j = 0; j < 16; j++) S[j] = 0.f;

    // L2 prefetch pointer (lanes 0..8 of warp 0)
    const float* pf = nullptr;
    size_t pfstride = 0;
    if (warp == 0 && lane < 9) {
        if (lane < 8) {
            const float* bases[4] = {egg, kg, qg, vg};
            pf = bases[lane >> 1] + h * DD + (lane & 1) * 32;
            pfstride = PP;
        } else {
            pf = bg + h;
            pfstride = HH;
        }
    }

    float ea[16], ka[16], qa[16], va, ba;
    float eb[16], kbf[16], qb[16], vb, bb;

#define LOADSTAGE(E, KA, QA, V, B, t)                                            \
    do {                                                                         \
        size_t off = (size_t)(t) * PP;                                           \
        _Pragma("unroll")                                                        \
        for (int j = 0; j < 16; j += 4) {                                        \
            *reinterpret_cast<float4*>(&E[j])  =                                 \
                *reinterpret_cast<const float4*>(ep + off + j);                  \
            *reinterpret_cast<float4*>(&KA[j]) =                                 \
                *reinterpret_cast<const float4*>(kp + off + j);                  \
            *reinterpret_cast<float4*>(&QA[j]) =                                 \
                *reinterpret_cast<const float4*>(qp + off + j);                  \
        }                                                                        \
        V = vpt[off];                                                            \
        B = bpt[(size_t)(t) * HH];                                               \
    } while (0)

    LOADSTAGE(ea, ka, qa, va, ba, 0);
    LOADSTAGE(eb, kbf, qb, vb, bb, 1);

    for (int t = 0; t < TT; t += 2) {
        if (pf) {
            int tp = t + 8;
            if (tp + 1 < TT) {
                const float* p0 = pf + (size_t)tp * pfstride;
                const float* p1 = pf + (size_t)(tp + 1) * pfstride;
                asm volatile("prefetch.global.L2 [%0];" :: "l"(p0));
                asm volatile("prefetch.global.L2 [%0];" :: "l"(p1));
            }
        }
        float ov = kda_step(S, ea, ka, qa, va, ba);
        if (quarter == 0) og[(size_t)t * PP + h * DD + col] = ov;
        if (t + 2 < TT) LOADSTAGE(ea, ka, qa, va, ba, t + 2);

        ov = kda_step(S, eb, kbf, qb, vb, bb);
        if (quarter == 0) og[(size_t)(t + 1) * PP + h * DD + col] = ov;
        if (t + 3 < TT) LOADSTAGE(eb, kbf, qb, vb, bb, t + 3);
    }
#undef LOADSTAGE
}

// ---------------------------------------------------------------------------
// Gated RMSNorm: o <- o * rsqrt(mean(o^2)+eps) * w[d] * sigmoid(g2)
// grid (T, H/8), block 256, one (t,h) per warp
// ---------------------------------------------------------------------------
__global__ void rms_gate_kernel(float* __restrict__ o,
                                const float* __restrict__ g2,
                                const float* __restrict__ wn)
{
    const int t    = blockIdx.x;
    const int h    = blockIdx.y * 8 + (threadIdx.x >> 5);
    const int lane = threadIdx.x & 31;
    size_t base = (size_t)t * PP + h * DD;

    float a = o[base + lane];
    float b = o[base + lane + 32];
    float ss = a * a + b * b;
    ss += __shfl_xor_sync(0xffffffffu, ss, 16);
    ss += __shfl_xor_sync(0xffffffffu, ss, 8);
    ss += __shfl_xor_sync(0xffffffffu, ss, 4);
    ss += __shfl_xor_sync(0xffffffffu, ss, 2);
    ss += __shfl_xor_sync(0xffffffffu, ss, 1);
    float r = rsqrtf(ss * (1.f / 64.f) + 1e-5f);

    float ga = g2[base + lane];
    float gb = g2[base + lane + 32];
    o[base + lane]      = a * r * wn[lane]      * (1.f / (1.f + __expf(-ga)));
    o[base + lane + 32] = b * r * wn[lane + 32] * (1.f / (1.f + __expf(-gb)));
}

// ---------------------------------------------------------------------------
// Host launcher
// ---------------------------------------------------------------------------
extern "C" void kernel_launch(void* const* d_in, const int* in_sizes, int n_in,
                              void* d_out, int out_size)
{
    const float* x    = (const float*)d_in[0];   // [T, HID]
    const float* Wq   = (const float*)d_in[1];   // [HID, P]
    const float* Wk   = (const float*)d_in[2];
    const float* Wv   = (const float*)d_in[3];
    const float* Wb   = (const float*)d_in[4];   // [HID, H]
    const float* Wfa  = (const float*)d_in[5];   // [HID, D]
    const float* Wfb  = (const float*)d_in[6];   // [D, P]
    const float* dtb  = (const float*)d_in[7];   // [P]
    const float* Alog = (const float*)d_in[8];   // [H]
    const float* Wga  = (const float*)d_in[9];   // [HID, D]
    const float* Wgb  = (const float*)d_in[10];  // [D, P]
    const float* cq   = (const float*)d_in[11];  // [P, 4]
    const float* ck   = (const float*)d_in[12];
    const float* cv   = (const float*)d_in[13];
    const float* wno  = (const float*)d_in[14];  // [D]
    const float* Wo   = (const float*)d_in[15];  // [P, HID]
    float* out = (float*)d_out;                  // [T, HID]

    // resolve scratch symbols once (before capture; cached thereafter)
    static float *pxq = nullptr, *pxk, *pxv, *pq, *pk, *pv, *pgl, *pg2, *po,
                 *pfa, *pga, *pbl;
    if (!pxq) {
        cudaGetSymbolAddress((void**)&pxq, d_xq);
        cudaGetSymbolAddress((void**)&pxk, d_xk);
        cudaGetSymbolAddress((void**)&pxv, d_xv);
        cudaGetSymbolAddress((void**)&pq,  d_q);
        cudaGetSymbolAddress((void**)&pk,  d_k);
        cudaGetSymbolAddress((void**)&pv,  d_v);
        cudaGetSymbolAddress((void**)&pgl, d_gl);
        cudaGetSymbolAddress((void**)&pg2, d_g2);
        cudaGetSymbolAddress((void**)&po,  d_o);
        cudaGetSymbolAddress((void**)&pfa, d_fa);
        cudaGetSymbolAddress((void**)&pga, d_ga);
        cudaGetSymbolAddress((void**)&pbl, d_bl);
    }

    dim3 blk(256);

    // big GEMMs: 128x128 tiles
    auto bigGrid = [](int M, int N) { return dim3((N + 127) / 128, (M + 127) / 128); };
    // skinny GEMMs: 32x64 tiles (N <= 64), maximizes block parallelism
    auto skGrid  = [](int M, int N) { return dim3((N + 63) / 64, (M + 31) / 32); };

    // 1-3: QKV projections
    sgemm_kernel<128,128,16,8,8><<<bigGrid(TT, PP), blk>>>(x, Wq, pxq, TT, PP, HIDD);
    sgemm_kernel<128,128,16,8,8><<<bigGrid(TT, PP), blk>>>(x, Wk, pxk, TT, PP, HIDD);
    sgemm_kernel<128,128,16,8,8><<<bigGrid(TT, PP), blk>>>(x, Wv, pxv, TT, PP, HIDD);

    // 4-6: low-rank gate inputs + beta
    sgemm_kernel<32,64,16,4,2><<<skGrid(TT, DD), blk>>>(x, Wfa, pfa, TT, DD, HIDD);
    sgemm_kernel<32,64,16,4,2><<<skGrid(TT, DD), blk>>>(x, Wga, pga, TT, DD, HIDD);
    sgemm_kernel<32,64,16,4,2><<<skGrid(TT, HH), blk>>>(x, Wb,  pbl, TT, HH, HIDD);

    // 7-8: gate expansions
    sgemm_kernel<128,128,16,8,8><<<bigGrid(TT, PP), blk>>>(pfa, Wfb, pgl, TT, PP, DD);
    sgemm_kernel<128,128,16,8,8><<<bigGrid(TT, PP), blk>>>(pga, Wgb, pg2, TT, PP, DD);

    // 9: decay epilogue (softplus + exp), in place on pgl
    decay_kernel<<<4096, 256>>>(pgl, dtb, Alog);

    // 10: conv + silu (+ l2norm)
    dim3 cgrid(TT, HH / 8);
    conv_silu_kernel<<<cgrid, blk>>>(pxq, cq, pq, 2);  // q: norm + scale
    conv_silu_kernel<<<cgrid, blk>>>(pxk, ck, pk, 1);  // k: norm
    conv_silu_kernel<<<cgrid, blk>>>(pxv, cv, pv, 0);  // v: plain

    // 11: sequential KDA scan (one block per head)
    kda_scan_kernel<<<HH, 256>>>(pq, pk, pv, pgl, pbl, po);

    // 12: gated RMSNorm in place
    rms_gate_kernel<<<cgrid, blk>>>(po, pg2, wno);

    // 13: output projection -> d_out
    sgemm_kernel<128,128,16,8,8><<<bigGrid(TT, HIDD), blk>>>(po, Wo, out, TT, HIDD, PP);

    (void)in_sizes; (void)n_in; (void)out_size;
}

// round 3
// speedup vs baseline: 1.9016x; 1.9016x over previous
#include <cuda_runtime.h>
#include <cuda_bf16.h>
#include <cstdint>

// ---------------------------------------------------------------------------
// Problem constants
// ---------------------------------------------------------------------------
#define TT   4096
#define HIDD 4096
#define HH   32
#define DD   64
#define PP   2048

// ---------------------------------------------------------------------------
// Device scratch
// ---------------------------------------------------------------------------
__device__ float d_xq[TT * PP];
__device__ float d_xk[TT * PP];
__device__ float d_xv[TT * PP];
__device__ float d_q [TT * PP];
__device__ float d_k [TT * PP];
__device__ float d_v [TT * PP];
__device__ float d_gl[TT * PP];
__device__ float d_g2[TT * PP];
__device__ float d_o [TT * PP];
__device__ float d_fa[TT * DD];
__device__ float d_ga[TT * DD];
__device__ float d_bl[TT * HH];
__device__ float d_sm[TT * 256];

__device__ __nv_bfloat16 d_xhi[TT * HIDD], d_xlo[TT * HIDD];
__device__ __nv_bfloat16 d_wqth[PP * HIDD], d_wqtl[PP * HIDD];
__device__ __nv_bfloat16 d_wkth[PP * HIDD], d_wktl[PP * HIDD];
__device__ __nv_bfloat16 d_wvth[PP * HIDD], d_wvtl[PP * HIDD];
__device__ __nv_bfloat16 d_woth[HIDD * PP], d_wotl[HIDD * PP];
__device__ __nv_bfloat16 d_wsmh[256 * HIDD], d_wsml[256 * HIDD];
__device__ __nv_bfloat16 d_ohi[TT * PP],  d_olo[TT * PP];

// ---------------------------------------------------------------------------
// cp.async / ldmatrix / mma helpers
// ---------------------------------------------------------------------------
__device__ __forceinline__ uint32_t smem_u32(const void* p) {
    uint32_t a;
    asm("{ .reg .u64 t; cvta.to.shared.u64 t, %1; cvt.u32.u64 %0, t; }"
        : "=r"(a) : "l"(p));
    return a;
}
#define CP_ASYNC16(smem, gptr) \
    asm volatile("cp.async.cg.shared.global [%0], [%1], 16;\n" \
                 :: "r"(smem), "l"(gptr))
#define CP_COMMIT() asm volatile("cp.async.commit_group;\n" ::: "memory")
#define CP_WAIT1()  asm volatile("cp.async.wait_group 1;\n" ::: "memory")
#define CP_WAIT0()  asm volatile("cp.async.wait_group 0;\n" ::: "memory")

#define LDMX4(r0, r1, r2, r3, addr)                                       \
    asm volatile("ldmatrix.sync.aligned.m8n8.x4.shared.b16 "              \
                 "{%0, %1, %2, %3}, [%4];"                                \
                 : "=r"(r0), "=r"(r1), "=r"(r2), "=r"(r3) : "r"(addr))

#define MMA16816(c0, c1, c2, c3, a0, a1, a2, a3, b0, b1)                  \
    asm volatile("mma.sync.aligned.m16n8k16.row.col.f32.bf16.bf16.f32 "   \
                 "{%0, %1, %2, %3}, {%4, %5, %6, %7}, {%8, %9}, "         \
                 "{%0, %1, %2, %3};"                                      \
                 : "+f"(c0), "+f"(c1), "+f"(c2), "+f"(c3)                 \
                 : "r"(a0), "r"(a1), "r"(a2), "r"(a3), "r"(b0), "r"(b1))

// ---------------------------------------------------------------------------
// bf16 HMMA GEMM, 3-pass split:  C = A0@B0 + A1@B1 + A2@B2  (fp32 out)
// A*: [M,K] bf16 row-major.  B*: [N,K] bf16 row-major (W^T).
// Block 128x128, BK=32, 8 warps (2x4), warp tile 64x32, 3-stage cp.async.
// ---------------------------------------------------------------------------
#define BKH     40                      // 32 halves + 8 pad (80 B rows)
#define STG_H   (2 * 128 * BKH)         // halves per stage (A then B)
#define NSTAGE  3

__global__ void __launch_bounds__(256)
mma_gemm_kernel(const __nv_bfloat16* __restrict__ A0, const __nv_bfloat16* __restrict__ A1,
                const __nv_bfloat16* __restrict__ A2,
                const __nv_bfloat16* __restrict__ B0, const __nv_bfloat16* __restrict__ B1,
                const __nv_bfloat16* __restrict__ B2,
                float* __restrict__ C, int K, int ldc)
{
    extern __shared__ __align__(16) __nv_bfloat16 smem[];
    const uint32_t sbase = smem_u32(smem);

    const int tid   = threadIdx.x;
    const int wid   = tid >> 5;
    const int lane  = tid & 31;
    const int warpM = wid >> 2;          // 0..1
    const int warpN = wid & 3;           // 0..3
    const int rowBase = blockIdx.y * 128;
    const int colBase = blockIdx.x * 128;

    const __nv_bfloat16* APs[3] = {A0, A1, A2};
    const __nv_bfloat16* BPs[3] = {B0, B1, B2};
    const int kChunks = K >> 5;          // K/32
    const int nIter   = 3 * kChunks;

    float acc[4][4][4];
#pragma unroll
    for (int i = 0; i < 4; i++)
#pragma unroll
        for (int j = 0; j < 4; j++)
#pragma unroll
            for (int r = 0; r < 4; r++) acc[i][j][r] = 0.f;

    // cp.async thread map: idx -> (row, 8-half chunk); 2 A ops + 2 B ops
    const int ldr = tid >> 2;            // 0..63
    const int ldc8 = (tid & 3) * 8;      // 0,8,16,24

#define LOAD_STAGE(j, s)                                                        \
    do {                                                                        \
        int _pass = (j) / kChunks;                                              \
        int _kOff = ((j) - _pass * kChunks) << 5;                               \
        const __nv_bfloat16* _Ap = APs[_pass];                                  \
        const __nv_bfloat16* _Bp = BPs[_pass];                                  \
        uint32_t _sA = sbase + (uint32_t)(s) * (STG_H * 2);                     \
        uint32_t _sB = _sA + 128 * BKH * 2;                                     \
        _Pragma("unroll")                                                       \
        for (int _i = 0; _i < 2; _i++) {                                        \
            int _r = ldr + _i * 64;                                             \
            CP_ASYNC16(_sA + (_r * BKH + ldc8) * 2,                             \
                       _Ap + (size_t)(rowBase + _r) * K + _kOff + ldc8);        \
        }                                                                       \
        _Pragma("unroll")                                                       \
        for (int _i = 0; _i < 2; _i++) {                                        \
            int _r = ldr + _i * 64;                                             \
            CP_ASYNC16(_sB + (_r * BKH + ldc8) * 2,                             \
                       _Bp + (size_t)(colBase + _r) * K + _kOff + ldc8);        \
        }                                                                       \
        CP_COMMIT();                                                            \
    } while (0)

    LOAD_STAGE(0, 0);
    LOAD_STAGE(1, 1);

    // fragment address offsets (constant per thread)
    const int aRow = (lane & 15);          // within 16-row tile
    const int aKof = (lane >> 4) * 8;      // 0 or 8
    const int bNof = ((lane >> 4) & 1) * 8 + (lane & 7);
    const int bKof = ((lane >> 3) & 1) * 8;

    int s = 0;
    for (int it = 0; it < nIter; it++) {
        CP_WAIT1();
        __syncthreads();
        int jn = it + 2;
        int sn = s + 2; if (sn >= NSTAGE) sn -= NSTAGE;
        if (jn < nIter) LOAD_STAGE(jn, sn);

        uint32_t aBase = sbase + (uint32_t)s * (STG_H * 2) +
                         (warpM * 64) * (BKH * 2);
        uint32_t bBase = sbase + (uint32_t)s * (STG_H * 2) + 128 * BKH * 2 +
                         (warpN * 32) * (BKH * 2);

#pragma unroll
        for (int kk = 0; kk < 2; kk++) {
            uint32_t a[4][4];
            uint32_t b[2][4];
#pragma unroll
            for (int mi = 0; mi < 4; mi++) {
                uint32_t ad = aBase + ((mi * 16 + aRow) * BKH + kk * 16 + aKof) * 2;
                LDMX4(a[mi][0], a[mi][1], a[mi][2], a[mi][3], ad);
            }
#pragma unroll
            for (int nb = 0; nb < 2; nb++) {
                uint32_t bd = bBase + ((nb * 16 + bNof) * BKH + kk * 16 + bKof) * 2;
                LDMX4(b[nb][0], b[nb][1], b[nb][2], b[nb][3], bd);
            }
#pragma unroll
            for (int mi = 0; mi < 4; mi++) {
#pragma unroll
                for (int ni = 0; ni < 4; ni++) {
                    int nb = ni >> 1;
                    int hi = (ni & 1) * 2;
                    MMA16816(acc[mi][ni][0], acc[mi][ni][1],
                             acc[mi][ni][2], acc[mi][ni][3],
                             a[mi][0], a[mi][1], a[mi][2], a[mi][3],
                             b[nb][hi], b[nb][hi + 1]);
                }
            }
        }
        __syncthreads();
        if (++s == NSTAGE) s = 0;
    }
    CP_WAIT0();

    // epilogue: direct fp32 stores
    const int erow = rowBase + warpM * 64 + (lane >> 2);
    const int ecol = colBase + warpN * 32 + (lane & 3) * 2;
#pragma unroll
    for (int mi = 0; mi < 4; mi++) {
#pragma unroll
        for (int ni = 0; ni < 4; ni++) {
            float* p0 = C + (size_t)(erow + mi * 16) * ldc + ecol + ni * 8;
            float* p1 = p0 + 8 * (size_t)ldc;
            *reinterpret_cast<float2*>(p0) = make_float2(acc[mi][ni][0], acc[mi][ni][1]);
            *reinterpret_cast<float2*>(p1) = make_float2(acc[mi][ni][2], acc[mi][ni][3]);
        }
    }
}

// ---------------------------------------------------------------------------
// Prep kernels
// ---------------------------------------------------------------------------
__global__ void split_rows_kernel(const float* __restrict__ x,
                                  __nv_bfloat16* __restrict__ hi,
                                  __nv_bfloat16* __restrict__ lo, size_t n)
{
    for (size_t i = (size_t)blockIdx.x * blockDim.x + threadIdx.x; i < n;
         i += (size_t)gridDim.x * blockDim.x) {
        float v = x[i];
        __nv_bfloat16 h = __float2bfloat16(v);
        hi[i] = h;
        lo[i] = __float2bfloat16(v - __bfloat162float(h));
    }
}

// in [R, C] fp32 -> out hi/lo [C, R] bf16
__global__ void transpose_split_kernel(const float* __restrict__ in,
                                       __nv_bfloat16* __restrict__ hi,
                                       __nv_bfloat16* __restrict__ lo,
                                       int R, int C)
{
    __shared__ float t[32][33];
    int c0 = blockIdx.x * 32, r0 = blockIdx.y * 32;
    int x = threadIdx.x, y = threadIdx.y;
#pragma unroll
    for (int i = 0; i < 32; i += 8)
        t[y + i][x] = in[(size_t)(r0 + y + i) * C + c0 + x];
    __syncthreads();
#pragma unroll
    for (int i = 0; i < 32; i += 8) {
        float v = t[x][y + i];
        __nv_bfloat16 h = __float2bfloat16(v);
        size_t idx = (size_t)(c0 + y + i) * R + r0 + x;
        hi[idx] = h;
        lo[idx] = __float2bfloat16(v - __bfloat162float(h));
    }
}

// pack Wfa[HID,64] | Wga[HID,64] | Wb[HID,32] -> W^T [256, HID] (zero pad)
__global__ void pack_small_kernel(const float* __restrict__ Wfa,
                                  const float* __restrict__ Wga,
                                  const float* __restrict__ Wb,
                                  __nv_bfloat16* __restrict__ hi,
                                  __nv_bfloat16* __restrict__ lo)
{
    size_t total = (size_t)256 * HIDD;
    for (size_t i = (size_t)blockIdx.x * blockDim.x + threadIdx.x; i < total;
         i += (size_t)gridDim.x * blockDim.x) {
        int n = (int)(i / HIDD);
        int k = (int)(i % HIDD);
        float v = 0.f;
        if (n < 64)       v = Wfa[(size_t)k * 64 + n];
        else if (n < 128) v = Wga[(size_t)k * 64 + (n - 64)];
        else if (n < 160) v = Wb[(size_t)k * 32 + (n - 128)];
        __nv_bfloat16 h = __float2bfloat16(v);
        hi[i] = h;
        lo[i] = __float2bfloat16(v - __bfloat162float(h));
    }
}

__global__ void extract_small_kernel(const float* __restrict__ sm,
                                     float* __restrict__ fa, float* __restrict__ ga,
                                     float* __restrict__ bl)
{
    size_t total = (size_t)TT * 160;
    for (size_t i = (size_t)blockIdx.x * blockDim.x + threadIdx.x; i < total;
         i += (size_t)gridDim.x * blockDim.x) {
        int m = (int)(i / 160);
        int c = (int)(i % 160);
        float v = sm[(size_t)m * 256 + c];
        if (c < 64)       fa[(size_t)m * 64 + c] = v;
        else if (c < 128) ga[(size_t)m * 64 + (c - 64)] = v;
        else              bl[(size_t)m * 32 + (c - 128)] = v;
    }
}

// ---------------------------------------------------------------------------
// SIMT fp32 GEMM (low-rank expansions, K=64)
// ---------------------------------------------------------------------------
template <int BM, int BN, int BK, int TM, int TN>
__global__ void __launch_bounds__(256)
sgemm_kernel(const float* __restrict__ A, const float* __restrict__ B,
             float* __restrict__ C, int M, int N, int K)
{
    __shared__ float As[BK][BM + 4];
    __shared__ float Bs[BK][BN];

    const int tid = threadIdx.x;
    const int tx  = tid % (BN / TN);
    const int ty  = tid / (BN / TN);
    const int rowBase = blockIdx.y * BM;
    const int colBase = blockIdx.x * BN;

    float acc[TM][TN];
#pragma unroll
    for (int i = 0; i < TM; i++)
#pragma unroll
        for (int j = 0; j < TN; j++) acc[i][j] = 0.f;

    constexpr int A4 = BM * BK / 4;
    constexpr int B4 = BK * BN / 4;

    for (int kb = 0; kb < K; kb += BK) {
        for (int i = tid; i < A4; i += 256) {
            int r  = i / (BK / 4);
            int c4 = (i % (BK / 4)) * 4;
            float4 v = make_float4(0.f, 0.f, 0.f, 0.f);
            int gr = rowBase + r;
            if (gr < M)
                v = *reinterpret_cast<const float4*>(&A[(size_t)gr * K + kb + c4]);
            As[c4 + 0][r] = v.x; As[c4 + 1][r] = v.y;
            As[c4 + 2][r] = v.z; As[c4 + 3][r] = v.w;
        }
        for (int i = tid; i < B4; i += 256) {
            int r  = i / (BN / 4);
            int c4 = (i % (BN / 4)) * 4;
            float4 v = make_float4(0.f, 0.f, 0.f, 0.f);
            int gc = colBase + c4;
            if (gc < N)
                v = *reinterpret_cast<const float4*>(&B[(size_t)(kb + r) * N + gc]);
            *reinterpret_cast<float4*>(&Bs[r][c4]) = v;
        }
        __syncthreads();

#pragma unroll
        for (int kk = 0; kk < BK; kk++) {
            float ra[TM], rb[TN];
#pragma unroll
            for (int i = 0; i < TM; i++) ra[i] = As[kk][ty * TM + i];
#pragma unroll
            for (int j = 0; j < TN; j++) rb[j] = Bs[kk][tx * TN + j];
#pragma unroll
            for (int i = 0; i < TM; i++)
#pragma unroll
                for (int j = 0; j < TN; j++)
                    acc[i][j] = fmaf(ra[i], rb[j], acc[i][j]);
        }
        __syncthreads();
    }

#pragma unroll
    for (int i = 0; i < TM; i++) {
        int r = rowBase + ty * TM + i;
        if (r >= M) continue;
#pragma unroll
        for (int j = 0; j < TN; j++) {
            int c = colBase + tx * TN + j;
            if (c < N) C[(size_t)r * N + c] = acc[i][j];
        }
    }
}

// ---------------------------------------------------------------------------
// conv+silu (+l2norm), decay, scan, rms
// ---------------------------------------------------------------------------
__global__ void conv_silu_kernel(const float* __restrict__ x,
                                 const float* __restrict__ w,
                                 float* __restrict__ y, int mode)
{
    const int t    = blockIdx.x;
    const int h    = blockIdx.y * 8 + (threadIdx.x >> 5);
    const int lane = threadIdx.x & 31;

    float val[2];
    float ss = 0.f;
#pragma unroll
    for (int e = 0; e < 2; e++) {
        int d = lane + e * 32;
        int p = h * DD + d;
        const float* xp = x + p;
        float w0 = w[p * 4 + 0], w1 = w[p * 4 + 1];
        float w2 = w[p * 4 + 2], w3 = w[p * 4 + 3];
        float acc = xp[(size_t)t * PP] * w3;
        if (t >= 1) acc = fmaf(xp[(size_t)(t - 1) * PP], w2, acc);
        if (t >= 2) acc = fmaf(xp[(size_t)(t - 2) * PP], w1, acc);
        if (t >= 3) acc = fmaf(xp[(size_t)(t - 3) * PP], w0, acc);
        float sv = acc / (1.f + __expf(-acc));
        val[e] = sv;
        ss += sv * sv;
    }
    if (mode > 0) {
        ss += __shfl_xor_sync(0xffffffffu, ss, 16);
        ss += __shfl_xor_sync(0xffffffffu, ss, 8);
        ss += __shfl_xor_sync(0xffffffffu, ss, 4);
        ss += __shfl_xor_sync(0xffffffffu, ss, 2);
        ss += __shfl_xor_sync(0xffffffffu, ss, 1);
        float r = rsqrtf(ss + 1e-6f);
        if (mode == 2) r *= 0.125f;
        val[0] *= r; val[1] *= r;
    }
    size_t base = (size_t)t * PP + h * DD;
    y[base + lane]      = val[0];
    y[base + lane + 32] = val[1];
}

__global__ void decay_kernel(float* __restrict__ gl,
                             const float* __restrict__ dtb,
                             const float* __restrict__ Alog)
{
    const size_t total = (size_t)TT * PP;
    for (size_t idx = (size_t)blockIdx.x * blockDim.x + threadIdx.x;
         idx < total; idx += (size_t)gridDim.x * blockDim.x) {
        int pr = (int)(idx & (PP - 1));
        int h  = pr >> 6;
        float xv = gl[idx] + dtb[pr];
        float sp = (xv > 20.f) ? xv : log1pf(expf(xv));
        gl[idx] = expf(-expf(Alog[h]) * sp);
    }
}

__device__ __forceinline__ float kda_step(float S[16],
                                          const float eg[16], const float kk[16],
                                          const float qq[16], float vv, float braw)
{
    float vp0 = 0.f, vp1 = 0.f, vp2 = 0.f, vp3 = 0.f;
#pragma unroll
    for (int j = 0; j < 16; j += 4) {
        float s0 = S[j + 0] * eg[j + 0]; S[j + 0] = s0; vp0 = fmaf(kk[j + 0], s0, vp0);
        float s1 = S[j + 1] * eg[j + 1]; S[j + 1] = s1; vp1 = fmaf(kk[j + 1], s1, vp1);
        float s2 = S[j + 2] * eg[j + 2]; S[j + 2] = s2; vp2 = fmaf(kk[j + 2], s2, vp2);
        float s3 = S[j + 3] * eg[j + 3]; S[j + 3] = s3; vp3 = fmaf(kk[j + 3], s3, vp3);
    }
    float vpred = (vp0 + vp1) + (vp2 + vp3);
    vpred += __shfl_xor_sync(0xffffffffu, vpred, 8);
    vpred += __shfl_xor_sync(0xffffffffu, vpred, 16);
    float b = 1.f / (1.f + __expf(-braw));
    float delta = (vv - vpred) * b;
    float o0 = 0.f, o1 = 0.f, o2 = 0.f, o3 = 0.f;
#pragma unroll
    for (int j = 0; j < 16; j += 4) {
        S[j + 0] = fmaf(kk[j + 0], delta, S[j + 0]); o0 = fmaf(qq[j + 0], S[j + 0], o0);
        S[j + 1] = fmaf(kk[j + 1], delta, S[j + 1]); o1 = fmaf(qq[j + 1], S[j + 1], o1);
        S[j + 2] = fmaf(kk[j + 2], delta, S[j + 2]); o2 = fmaf(qq[j + 2], S[j + 2], o2);
        S[j + 3] = fmaf(kk[j + 3], delta, S[j + 3]); o3 = fmaf(qq[j + 3], S[j + 3], o3);
    }
    float ov = (o0 + o1) + (o2 + o3);
    ov += __shfl_xor_sync(0xffffffffu, ov, 8);
    ov += __shfl_xor_sync(0xffffffffu, ov, 16);
    return ov;
}

__global__ void __launch_bounds__(256, 1)
kda_scan_kernel(const float* __restrict__ qg, const float* __restrict__ kg,
                const float* __restrict__ vg, const float* __restrict__ egg,
                const float* __restrict__ bg, float* __restrict__ og)
{
    const int h       = blockIdx.x;
    const int warp    = threadIdx.x >> 5;
    const int lane    = threadIdx.x & 31;
    const int quarter = lane >> 3;
    const int col     = (warp << 3) + (lane & 7);
    const int kb      = quarter << 4;

    const float* ep  = egg + h * DD + kb;
    const float* kp  = kg  + h * DD + kb;
    const float* qp  = qg  + h * DD + kb;
    const float* vpt = vg  + h * DD + col;
    const float* bpt = bg  + h;

    float S[16];
#pragma unroll
    for (int j = 0; j < 16; j++) S[j] = 0.f;

    const float* pf = nullptr;
    size_t pfstride = 0;
    if (warp == 0 && lane < 9) {
        if (lane < 8) {
            const float* bases[4] = {egg, kg, qg, vg};
            pf = bases[lane >> 1] + h * DD + (lane & 1) * 32;
            pfstride = PP;
        } else {
            pf = bg + h;
            pfstride = HH;
        }
    }

    float ea[16], ka[16], qa[16], va, ba;
    float eb[16], kbf[16], qb[16], vb, bb;

#define LOADSTAGE(E, KA, QA, V, B, t)                                            \
    do {                                                                         \
        size_t off = (size_t)(t) * PP;                                           \
        _Pragma("unroll")                                                        \
        for (int j = 0; j < 16; j += 4) {                                        \
            *reinterpret_cast<float4*>(&E[j])  =                                 \
                *reinterpret_cast<const float4*>(ep + off + j);                  \
            *reinterpret_cast<float4*>(&KA[j]) =                                 \
                *reinterpret_cast<const float4*>(kp + off + j);                  \
            *reinterpret_cast<float4*>(&QA[j]) =                                 \
                *reinterpret_cast<const float4*>(qp + off + j);                  \
        }                                                                        \
        V = vpt[off];                                                            \
        B = bpt[(size_t)(t) * HH];                                               \
    } while (0)

    LOADSTAGE(ea, ka, qa, va, ba, 0);
    LOADSTAGE(eb, kbf, qb, vb, bb, 1);

    for (int t = 0; t < TT; t += 2) {
        if (pf) {
            int tp = t + 8;
            if (tp + 1 < TT) {
                const float* p0 = pf + (size_t)tp * pfstride;
                const float* p1 = pf + (size_t)(tp + 1) * pfstride;
                asm volatile("prefetch.global.L2 [%0];" :: "l"(p0));
                asm volatile("prefetch.global.L2 [%0];" :: "l"(p1));
            }
        }
        float ov = kda_step(S, ea, ka, qa, va, ba);
        if (quarter == 0) og[(size_t)t * PP + h * DD + col] = ov;
        if (t + 2 < TT) LOADSTAGE(ea, ka, qa, va, ba, t + 2);

        ov = kda_step(S, eb, kbf, qb, vb, bb);
        if (quarter == 0) og[(size_t)(t + 1) * PP + h * DD + col] = ov;
        if (t + 3 < TT) LOADSTAGE(eb, kbf, qb, vb, bb, t + 3);
    }
#undef LOADSTAGE
}

__global__ void rms_gate_kernel(float* __restrict__ o,
                                const float* __restrict__ g2,
                                const float* __restrict__ wn)
{
    const int t    = blockIdx.x;
    const int h    = blockIdx.y * 8 + (threadIdx.x >> 5);
    const int lane = threadIdx.x & 31;
    size_t base = (size_t)t * PP + h * DD;

    float a = o[base + lane];
    float b = o[base + lane + 32];
    float ss = a * a + b * b;
    ss += __shfl_xor_sync(0xffffffffu, ss, 16);
    ss += __shfl_xor_sync(0xffffffffu, ss, 8);
    ss += __shfl_xor_sync(0xffffffffu, ss, 4);
    ss += __shfl_xor_sync(0xffffffffu, ss, 2);
    ss += __shfl_xor_sync(0xffffffffu, ss, 1);
    float r = rsqrtf(ss * (1.f / 64.f) + 1e-5f);

    float ga = g2[base + lane];
    float gb = g2[base + lane + 32];
    o[base + lane]      = a * r * wn[lane]      * (1.f / (1.f + __expf(-ga)));
    o[base + lane + 32] = b * r * wn[lane + 32] * (1.f / (1.f + __expf(-gb)));
}

// ---------------------------------------------------------------------------
// Host launcher
// ---------------------------------------------------------------------------
extern "C" void kernel_launch(void* const* d_in, const int* in_sizes, int n_in,
                              void* d_out, int out_size)
{
    const float* x    = (const float*)d_in[0];
    const float* Wq   = (const float*)d_in[1];
    const float* Wk   = (const float*)d_in[2];
    const float* Wv   = (const float*)d_in[3];
    const float* Wb   = (const float*)d_in[4];
    const float* Wfa  = (const float*)d_in[5];
    const float* Wfb  = (const float*)d_in[6];
    const float* dtb  = (const float*)d_in[7];
    const float* Alog = (const float*)d_in[8];
    const float* Wga  = (const float*)d_in[9];
    const float* Wgb  = (const float*)d_in[10];
    const float* cq   = (const float*)d_in[11];
    const float* ck   = (const float*)d_in[12];
    const float* cv   = (const float*)d_in[13];
    const float* wno  = (const float*)d_in[14];
    const float* Wo   = (const float*)d_in[15];
    float* out = (float*)d_out;

    static float *pxq = nullptr, *pxk, *pxv, *pq, *pk, *pv, *pgl, *pg2, *po,
                 *pfa, *pga, *pbl, *psm;
    static __nv_bfloat16 *pxhi, *pxlo, *pwqth, *pwqtl, *pwkth, *pwktl,
                         *pwvth, *pwvtl, *pwoth, *pwotl, *pwsmh, *pwsml,
                         *pohi, *polo;
    if (!pxq) {
        cudaGetSymbolAddress((void**)&pxq, d_xq);
        cudaGetSymbolAddress((void**)&pxk, d_xk);
        cudaGetSymbolAddress((void**)&pxv, d_xv);
        cudaGetSymbolAddress((void**)&pq,  d_q);
        cudaGetSymbolAddress((void**)&pk,  d_k);
        cudaGetSymbolAddress((void**)&pv,  d_v);
        cudaGetSymbolAddress((void**)&pgl, d_gl);
        cudaGetSymbolAddress((void**)&pg2, d_g2);
        cudaGetSymbolAddress((void**)&po,  d_o);
        cudaGetSymbolAddress((void**)&pfa, d_fa);
        cudaGetSymbolAddress((void**)&pga, d_ga);
        cudaGetSymbolAddress((void**)&pbl, d_bl);
        cudaGetSymbolAddress((void**)&psm, d_sm);
        cudaGetSymbolAddress((void**)&pxhi, d_xhi);
        cudaGetSymbolAddress((void**)&pxlo, d_xlo);
        cudaGetSymbolAddress((void**)&pwqth, d_wqth);
        cudaGetSymbolAddress((void**)&pwqtl, d_wqtl);
        cudaGetSymbolAddress((void**)&pwkth, d_wkth);
        cudaGetSymbolAddress((void**)&pwktl, d_wktl);
        cudaGetSymbolAddress((void**)&pwvth, d_wvth);
        cudaGetSymbolAddress((void**)&pwvtl, d_wvtl);
        cudaGetSymbolAddress((void**)&pwoth, d_woth);
        cudaGetSymbolAddress((void**)&pwotl, d_wotl);
        cudaGetSymbolAddress((void**)&pwsmh, d_wsmh);
        cudaGetSymbolAddress((void**)&pwsml, d_wsml);
        cudaGetSymbolAddress((void**)&pohi, d_ohi);
        cudaGetSymbolAddress((void**)&polo, d_olo);
        cudaFuncSetAttribute(mma_gemm_kernel,
                             cudaFuncAttributeMaxDynamicSharedMemorySize,
                             NSTAGE * STG_H * 2);
    }

    dim3 blk(256);
    const size_t smemMMA = NSTAGE * STG_H * 2;   // 61440 B

    // ---- prep: bf16 splits + weight transposes ----
    split_rows_kernel<<<2048, 256>>>(x, pxhi, pxlo, (size_t)TT * HIDD);
    transpose_split_kernel<<<dim3(PP / 32, HIDD / 32), dim3(32, 8)>>>(Wq, pwqth, pwqtl, HIDD, PP);
    transpose_split_kernel<<<dim3(PP / 32, HIDD / 32), dim3(32, 8)>>>(Wk, pwkth, pwktl, HIDD, PP);
    transpose_split_kernel<<<dim3(PP / 32, HIDD / 32), dim3(32, 8)>>>(Wv, pwvth, pwvtl, HIDD, PP);
    transpose_split_kernel<<<dim3(HIDD / 32, PP / 32), dim3(32, 8)>>>(Wo, pwoth, pwotl, PP, HIDD);
    pack_small_kernel<<<1024, 256>>>(Wfa, Wga, Wb, pwsmh, pwsml);

    // ---- big GEMMs on tensor cores (3-pass bf16 split) ----
    dim3 gQKV(PP / 128, TT / 128);
    mma_gemm_kernel<<<gQKV, blk, smemMMA>>>(pxhi, pxhi, pxlo, pwqth, pwqtl, pwqth, pxq, HIDD, PP);
    mma_gemm_kernel<<<gQKV, blk, smemMMA>>>(pxhi, pxhi, pxlo, pwkth, pwktl, pwkth, pxk, HIDD, PP);
    mma_gemm_kernel<<<gQKV, blk, smemMMA>>>(pxhi, pxhi, pxlo, pwvth, pwvtl, pwvth, pxv, HIDD, PP);

    // packed small projections (fa|ga|beta), N=256
    mma_gemm_kernel<<<dim3(2, TT / 128), blk, smemMMA>>>(pxhi, pxhi, pxlo,
                                                         pwsmh, pwsml, pwsmh,
                                                         psm, HIDD, 256);
    extract_small_kernel<<<1024, 256>>>(psm, pfa, pga, pbl);

    // ---- low-rank expansions (K=64, SIMT) ----
    dim3 gExp(PP / 128, TT / 128);
    sgemm_kernel<128, 128, 16, 8, 8><<<gExp, blk>>>(pfa, Wfb, pgl, TT, PP, DD);
    sgemm_kernel<128, 128, 16, 8, 8><<<gExp, blk>>>(pga, Wgb, pg2, TT, PP, DD);

    // ---- elementwise / scan ----
    decay_kernel<<<4096, 256>>>(pgl, dtb, Alog);
    dim3 cgrid(TT, HH / 8);
    conv_silu_kernel<<<cgrid, blk>>>(pxq, cq, pq, 2);
    conv_silu_kernel<<<cgrid, blk>>>(pxk, ck, pk, 1);
    conv_silu_kernel<<<cgrid, blk>>>(pxv, cv, pv, 0);
    kda_scan_kernel<<<HH, 256>>>(pq, pk, pv, pgl, pbl, po);
    rms_gate_kernel<<<cgrid, blk>>>(po, pg2, wno);

    // ---- output projection on tensor cores ----
    split_rows_kernel<<<2048, 256>>>(po, pohi, polo, (size_t)TT * PP);
    mma_gemm_kernel<<<dim3(HIDD / 128, TT / 128), blk, smemMMA>>>(pohi, pohi, polo,
                                                                  pwoth, pwotl, pwoth,
                                                                  out, PP, HIDD);

    (void)in_sizes; (void)n_in; (void)out_size;
}

// round 4
// speedup vs baseline: 2.4065x; 1.2655x over previous
#include <cuda_runtime.h>
#include <cuda_bf16.h>
#include <cstdint>

// ---------------------------------------------------------------------------
// Problem constants
// ---------------------------------------------------------------------------
#define TT   4096
#define HIDD 4096
#define HH   32
#define DD   64
#define PP   2048
#define NCMB 6400        // combined QKV+small output columns: 3*2048 + 256

// ---------------------------------------------------------------------------
// Device scratch
// ---------------------------------------------------------------------------
__device__ float d_xc[TT * NCMB];        // combined qkv|small projection out
__device__ float d_q [TT * PP];
__device__ float d_k [TT * PP];
__device__ float d_v [TT * PP];
__device__ float d_gl[TT * PP];
__device__ float d_g2[TT * PP];
__device__ float d_o [TT * PP];
__device__ float d_fa[TT * DD];
__device__ float d_ga[TT * DD];
__device__ float d_bl[TT * HH];

__device__ __nv_bfloat16 d_xhi[TT * HIDD], d_xlo[TT * HIDD];
__device__ __nv_bfloat16 d_wch[(size_t)NCMB * HIDD], d_wcl[(size_t)NCMB * HIDD];
__device__ __nv_bfloat16 d_woth[HIDD * PP], d_wotl[HIDD * PP];
__device__ __nv_bfloat16 d_ohi[TT * PP],  d_olo[TT * PP];

// ---------------------------------------------------------------------------
// cp.async / ldmatrix / mma helpers
// ---------------------------------------------------------------------------
__device__ __forceinline__ uint32_t smem_u32(const void* p) {
    uint32_t a;
    asm("{ .reg .u64 t; cvta.to.shared.u64 t, %1; cvt.u32.u64 %0, t; }"
        : "=r"(a) : "l"(p));
    return a;
}
#define CP_ASYNC16(smem, gptr) \
    asm volatile("cp.async.cg.shared.global [%0], [%1], 16;\n" \
                 :: "r"(smem), "l"(gptr))
#define CP_COMMIT() asm volatile("cp.async.commit_group;\n" ::: "memory")
#define CP_WAIT2()  asm volatile("cp.async.wait_group 2;\n" ::: "memory")
#define CP_WAIT0()  asm volatile("cp.async.wait_group 0;\n" ::: "memory")

#define LDMX4(r0, r1, r2, r3, addr)                                       \
    asm volatile("ldmatrix.sync.aligned.m8n8.x4.shared.b16 "              \
                 "{%0, %1, %2, %3}, [%4];"                                \
                 : "=r"(r0), "=r"(r1), "=r"(r2), "=r"(r3) : "r"(addr))

#define MMA16816(c0, c1, c2, c3, a0, a1, a2, a3, b0, b1)                  \
    asm volatile("mma.sync.aligned.m16n8k16.row.col.f32.bf16.bf16.f32 "   \
                 "{%0, %1, %2, %3}, {%4, %5, %6, %7}, {%8, %9}, "         \
                 "{%0, %1, %2, %3};"                                      \
                 : "+f"(c0), "+f"(c1), "+f"(c2), "+f"(c3)                 \
                 : "r"(a0), "r"(a1), "r"(a2), "r"(a3), "r"(b0), "r"(b1))

// ---------------------------------------------------------------------------
// bf16 HMMA GEMM, 3-pass split:  C = A0@B0 + A1@B1 + A2@B2  (fp32 out)
// A*: [M,K] bf16 row-major.  B*: [N,K] bf16 row-major (W^T).
// Block 128x128, BK=32, 8 warps (2x4), warp tile 64x32.
// 4-stage cp.async pipeline, ONE __syncthreads per K-chunk.
// ---------------------------------------------------------------------------
#define BKH     40                      // 32 halves + 8 pad (80 B rows)
#define STG_H   (2 * 128 * BKH)         // halves per stage (A then B)
#define NSTAGE  4

__global__ void __launch_bounds__(256, 2)
mma_gemm_kernel(const __nv_bfloat16* __restrict__ A0, const __nv_bfloat16* __restrict__ A1,
                const __nv_bfloat16* __restrict__ A2,
                const __nv_bfloat16* __restrict__ B0, const __nv_bfloat16* __restrict__ B1,
                const __nv_bfloat16* __restrict__ B2,
                float* __restrict__ C, int K, int ldc)
{
    extern __shared__ __align__(16) __nv_bfloat16 smem[];
    const uint32_t sbase = smem_u32(smem);

    const int tid   = threadIdx.x;
    const int wid   = tid >> 5;
    const int lane  = tid & 31;
    const int warpM = wid >> 2;          // 0..1
    const int warpN = wid & 3;           // 0..3
    const int rowBase = blockIdx.y * 128;
    const int colBase = blockIdx.x * 128;

    const __nv_bfloat16* APs[3] = {A0, A1, A2};
    const __nv_bfloat16* BPs[3] = {B0, B1, B2};
    const int kChunks = K >> 5;          // K/32
    const int nIter   = 3 * kChunks;

    float acc[4][4][4];
#pragma unroll
    for (int i = 0; i < 4; i++)
#pragma unroll
        for (int j = 0; j < 4; j++)
#pragma unroll
            for (int r = 0; r < 4; r++) acc[i][j][r] = 0.f;

    const int ldr  = tid >> 2;           // 0..63
    const int ldc8 = (tid & 3) * 8;      // 0,8,16,24

#define LOAD_STAGE(j, s)                                                        \
    do {                                                                        \
        int _pass = (j) / kChunks;                                              \
        int _kOff = ((j) - _pass * kChunks) << 5;                               \
        const __nv_bfloat16* _Ap = APs[_pass];                                  \
        const __nv_bfloat16* _Bp = BPs[_pass];                                  \
        uint32_t _sA = sbase + (uint32_t)(s) * (STG_H * 2);                     \
        uint32_t _sB = _sA + 128 * BKH * 2;                                     \
        _Pragma("unroll")                                                       \
        for (int _i = 0; _i < 2; _i++) {                                        \
            int _r = ldr + _i * 64;                                             \
            CP_ASYNC16(_sA + (_r * BKH + ldc8) * 2,                             \
                       _Ap + (size_t)(rowBase + _r) * K + _kOff + ldc8);        \
        }                                                                       \
        _Pragma("unroll")                                                       \
        for (int _i = 0; _i < 2; _i++) {                                        \
            int _r = ldr + _i * 64;                                             \
            CP_ASYNC16(_sB + (_r * BKH + ldc8) * 2,                             \
                       _Bp + (size_t)(colBase + _r) * K + _kOff + ldc8);        \
        }                                                                       \
        CP_COMMIT();                                                            \
    } while (0)

    LOAD_STAGE(0, 0);
    LOAD_STAGE(1, 1);
    LOAD_STAGE(2, 2);

    const int aRow = (lane & 15);
    const int aKof = (lane >> 4) * 8;
    const int bNof = ((lane >> 4) & 1) * 8 + (lane & 7);
    const int bKof = ((lane >> 3) & 1) * 8;

    int s = 0;
    for (int it = 0; it < nIter; it++) {
        CP_WAIT2();
        __syncthreads();
        // load into stage (s+3)&3 — that stage was computed in iteration it-1,
        // and the barrier above orders it after all warps finished it.
        int jn = it + 3;
        if (jn < nIter) {
            int sn = (s + 3) & 3;
            LOAD_STAGE(jn, sn);
        } else {
            CP_COMMIT();     // keep group accounting aligned with CP_WAIT2
        }

        uint32_t aBase = sbase + (uint32_t)s * (STG_H * 2) +
                         (warpM * 64) * (BKH * 2);
        uint32_t bBase = sbase + (uint32_t)s * (STG_H * 2) + 128 * BKH * 2 +
                         (warpN * 32) * (BKH * 2);

#pragma unroll
        for (int kk = 0; kk < 2; kk++) {
            uint32_t a[4][4];
            uint32_t b[2][4];
#pragma unroll
            for (int mi = 0; mi < 4; mi++) {
                uint32_t ad = aBase + ((mi * 16 + aRow) * BKH + kk * 16 + aKof) * 2;
                LDMX4(a[mi][0], a[mi][1], a[mi][2], a[mi][3], ad);
            }
#pragma unroll
            for (int nb = 0; nb < 2; nb++) {
                uint32_t bd = bBase + ((nb * 16 + bNof) * BKH + kk * 16 + bKof) * 2;
                LDMX4(b[nb][0], b[nb][1], b[nb][2], b[nb][3], bd);
            }
#pragma unroll
            for (int mi = 0; mi < 4; mi++) {
#pragma unroll
                for (int ni = 0; ni < 4; ni++) {
                    int nb = ni >> 1;
                    int hi = (ni & 1) * 2;
                    MMA16816(acc[mi][ni][0], acc[mi][ni][1],
                             acc[mi][ni][2], acc[mi][ni][3],
                             a[mi][0], a[mi][1], a[mi][2], a[mi][3],
                             b[nb][hi], b[nb][hi + 1]);
                }
            }
        }
        s = (s + 1) & 3;
    }
    CP_WAIT0();

    const int erow = rowBase + warpM * 64 + (lane >> 2);
    const int ecol = colBase + warpN * 32 + (lane & 3) * 2;
#pragma unroll
    for (int mi = 0; mi < 4; mi++) {
#pragma unroll
        for (int ni = 0; ni < 4; ni++) {
            float* p0 = C + (size_t)(erow + mi * 16) * ldc + ecol + ni * 8;
            float* p1 = p0 + 8 * (size_t)ldc;
            *reinterpret_cast<float2*>(p0) = make_float2(acc[mi][ni][0], acc[mi][ni][1]);
            *reinterpret_cast<float2*>(p1) = make_float2(acc[mi][ni][2], acc[mi][ni][3]);
        }
    }
}

// ---------------------------------------------------------------------------
// Prep kernels
// ---------------------------------------------------------------------------
__global__ void split_rows_kernel(const float* __restrict__ x,
                                  __nv_bfloat16* __restrict__ hi,
                                  __nv_bfloat16* __restrict__ lo, size_t n)
{
    for (size_t i = (size_t)blockIdx.x * blockDim.x + threadIdx.x; i < n;
         i += (size_t)gridDim.x * blockDim.x) {
        float v = x[i];
        __nv_bfloat16 h = __float2bfloat16(v);
        hi[i] = h;
        lo[i] = __float2bfloat16(v - __bfloat162float(h));
    }
}

// in [R, C] fp32 -> out hi/lo [C, R] bf16
__global__ void transpose_split_kernel(const float* __restrict__ in,
                                       __nv_bfloat16* __restrict__ hi,
                                       __nv_bfloat16* __restrict__ lo,
                                       int R, int C)
{
    __shared__ float t[32][33];
    int c0 = blockIdx.x * 32, r0 = blockIdx.y * 32;
    int x = threadIdx.x, y = threadIdx.y;
#pragma unroll
    for (int i = 0; i < 32; i += 8)
        t[y + i][x] = in[(size_t)(r0 + y + i) * C + c0 + x];
    __syncthreads();
#pragma unroll
    for (int i = 0; i < 32; i += 8) {
        float v = t[x][y + i];
        __nv_bfloat16 h = __float2bfloat16(v);
        size_t idx = (size_t)(c0 + y + i) * R + r0 + x;
        hi[idx] = h;
        lo[idx] = __float2bfloat16(v - __bfloat162float(h));
    }
}

// pack Wfa[HID,64] | Wga[HID,64] | Wb[HID,32] -> W^T [256, HID] (zero pad)
__global__ void pack_small_kernel(const float* __restrict__ Wfa,
                                  const float* __restrict__ Wga,
                                  const float* __restrict__ Wb,
                                  __nv_bfloat16* __restrict__ hi,
                                  __nv_bfloat16* __restrict__ lo)
{
    size_t total = (size_t)256 * HIDD;
    for (size_t i = (size_t)blockIdx.x * blockDim.x + threadIdx.x; i < total;
         i += (size_t)gridDim.x * blockDim.x) {
        int n = (int)(i / HIDD);
        int k = (int)(i % HIDD);
        float v = 0.f;
        if (n < 64)       v = Wfa[(size_t)k * 64 + n];
        else if (n < 128) v = Wga[(size_t)k * 64 + (n - 64)];
        else if (n < 160) v = Wb[(size_t)k * 32 + (n - 128)];
        __nv_bfloat16 h = __float2bfloat16(v);
        hi[i] = h;
        lo[i] = __float2bfloat16(v - __bfloat162float(h));
    }
}

// extract fa/ga/beta from combined [T, NCMB] GEMM output (cols 6144..6303)
__global__ void extract_small_kernel(const float* __restrict__ xc,
                                     float* __restrict__ fa, float* __restrict__ ga,
                                     float* __restrict__ bl)
{
    size_t total = (size_t)TT * 160;
    for (size_t i = (size_t)blockIdx.x * blockDim.x + threadIdx.x; i < total;
         i += (size_t)gridDim.x * blockDim.x) {
        int m = (int)(i / 160);
        int c = (int)(i % 160);
        float v = xc[(size_t)m * NCMB + 6144 + c];
        if (c < 64)       fa[(size_t)m * 64 + c] = v;
        else if (c < 128) ga[(size_t)m * 64 + (c - 64)] = v;
        else              bl[(size_t)m * 32 + (c - 128)] = v;
    }
}

// ---------------------------------------------------------------------------
// SIMT fp32 GEMM (low-rank expansions, K=64)
// ---------------------------------------------------------------------------
template <int BM, int BN, int BK, int TM, int TN>
__global__ void __launch_bounds__(256)
sgemm_kernel(const float* __restrict__ A, const float* __restrict__ B,
             float* __restrict__ C, int M, int N, int K)
{
    __shared__ float As[BK][BM + 4];
    __shared__ float Bs[BK][BN];

    const int tid = threadIdx.x;
    const int tx  = tid % (BN / TN);
    const int ty  = tid / (BN / TN);
    const int rowBase = blockIdx.y * BM;
    const int colBase = blockIdx.x * BN;

    float acc[TM][TN];
#pragma unroll
    for (int i = 0; i < TM; i++)
#pragma unroll
        for (int j = 0; j < TN; j++) acc[i][j] = 0.f;

    constexpr int A4 = BM * BK / 4;
    constexpr int B4 = BK * BN / 4;

    for (int kb = 0; kb < K; kb += BK) {
        for (int i = tid; i < A4; i += 256) {
            int r  = i / (BK / 4);
            int c4 = (i % (BK / 4)) * 4;
            float4 v = make_float4(0.f, 0.f, 0.f, 0.f);
            int gr = rowBase + r;
            if (gr < M)
                v = *reinterpret_cast<const float4*>(&A[(size_t)gr * K + kb + c4]);
            As[c4 + 0][r] = v.x; As[c4 + 1][r] = v.y;
            As[c4 + 2][r] = v.z; As[c4 + 3][r] = v.w;
        }
        for (int i = tid; i < B4; i += 256) {
            int r  = i / (BN / 4);
            int c4 = (i % (BN / 4)) * 4;
            float4 v = make_float4(0.f, 0.f, 0.f, 0.f);
            int gc = colBase + c4;
            if (gc < N)
                v = *reinterpret_cast<const float4*>(&B[(size_t)(kb + r) * N + gc]);
            *reinterpret_cast<float4*>(&Bs[r][c4]) = v;
        }
        __syncthreads();

#pragma unroll
        for (int kk = 0; kk < BK; kk++) {
            float ra[TM], rb[TN];
#pragma unroll
            for (int i = 0; i < TM; i++) ra[i] = As[kk][ty * TM + i];
#pragma unroll
            for (int j = 0; j < TN; j++) rb[j] = Bs[kk][tx * TN + j];
#pragma unroll
            for (int i = 0; i < TM; i++)
#pragma unroll
                for (int j = 0; j < TN; j++)
                    acc[i][j] = fmaf(ra[i], rb[j], acc[i][j]);
        }
        __syncthreads();
    }

#pragma unroll
    for (int i = 0; i < TM; i++) {
        int r = rowBase + ty * TM + i;
        if (r >= M) continue;
#pragma unroll
        for (int j = 0; j < TN; j++) {
            int c = colBase + tx * TN + j;
            if (c < N) C[(size_t)r * N + c] = acc[i][j];
        }
    }
}

// ---------------------------------------------------------------------------
// conv+silu (+l2norm) — x has row stride ldx (combined buffer)
// ---------------------------------------------------------------------------
__global__ void conv_silu_kernel(const float* __restrict__ x, int ldx,
                                 const float* __restrict__ w,
                                 float* __restrict__ y, int mode)
{
    const int t    = blockIdx.x;
    const int h    = blockIdx.y * 8 + (threadIdx.x >> 5);
    const int lane = threadIdx.x & 31;

    float val[2];
    float ss = 0.f;
#pragma unroll
    for (int e = 0; e < 2; e++) {
        int d = lane + e * 32;
        int p = h * DD + d;
        const float* xp = x + p;
        float w0 = w[p * 4 + 0], w1 = w[p * 4 + 1];
        float w2 = w[p * 4 + 2], w3 = w[p * 4 + 3];
        float acc = xp[(size_t)t * ldx] * w3;
        if (t >= 1) acc = fmaf(xp[(size_t)(t - 1) * ldx], w2, acc);
        if (t >= 2) acc = fmaf(xp[(size_t)(t - 2) * ldx], w1, acc);
        if (t >= 3) acc = fmaf(xp[(size_t)(t - 3) * ldx], w0, acc);
        float sv = acc / (1.f + __expf(-acc));
        val[e] = sv;
        ss += sv * sv;
    }
    if (mode > 0) {
        ss += __shfl_xor_sync(0xffffffffu, ss, 16);
        ss += __shfl_xor_sync(0xffffffffu, ss, 8);
        ss += __shfl_xor_sync(0xffffffffu, ss, 4);
        ss += __shfl_xor_sync(0xffffffffu, ss, 2);
        ss += __shfl_xor_sync(0xffffffffu, ss, 1);
        float r = rsqrtf(ss + 1e-6f);
        if (mode == 2) r *= 0.125f;
        val[0] *= r; val[1] *= r;
    }
    size_t base = (size_t)t * PP + h * DD;
    y[base + lane]      = val[0];
    y[base + lane + 32] = val[1];
}

__global__ void decay_kernel(float* __restrict__ gl,
                             const float* __restrict__ dtb,
                             const float* __restrict__ Alog)
{
    const size_t total = (size_t)TT * PP;
    for (size_t idx = (size_t)blockIdx.x * blockDim.x + threadIdx.x;
         idx < total; idx += (size_t)gridDim.x * blockDim.x) {
        int pr = (int)(idx & (PP - 1));
        int h  = pr >> 6;
        float xv = gl[idx] + dtb[pr];
        float sp = (xv > 20.f) ? xv : log1pf(expf(xv));
        gl[idx] = expf(-expf(Alog[h]) * sp);
    }
}

__device__ __forceinline__ float kda_step(float S[16],
                                          const float eg[16], const float kk[16],
                                          const float qq[16], float vv, float braw)
{
    float vp0 = 0.f, vp1 = 0.f, vp2 = 0.f, vp3 = 0.f;
#pragma unroll
    for (int j = 0; j < 16; j += 4) {
        float s0 = S[j + 0] * eg[j + 0]; S[j + 0] = s0; vp0 = fmaf(kk[j + 0], s0, vp0);
        float s1 = S[j + 1] * eg[j + 1]; S[j + 1] = s1; vp1 = fmaf(kk[j + 1], s1, vp1);
        float s2 = S[j + 2] * eg[j + 2]; S[j + 2] = s2; vp2 = fmaf(kk[j + 2], s2, vp2);
        float s3 = S[j + 3] * eg[j + 3]; S[j + 3] = s3; vp3 = fmaf(kk[j + 3], s3, vp3);
    }
    float vpred = (vp0 + vp1) + (vp2 + vp3);
    vpred += __shfl_xor_sync(0xffffffffu, vpred, 8);
    vpred += __shfl_xor_sync(0xffffffffu, vpred, 16);
    float b = 1.f / (1.f + __expf(-braw));
    float delta = (vv - vpred) * b;
    float o0 = 0.f, o1 = 0.f, o2 = 0.f, o3 = 0.f;
#pragma unroll
    for (int j = 0; j < 16; j += 4) {
        S[j + 0] = fmaf(kk[j + 0], delta, S[j + 0]); o0 = fmaf(qq[j + 0], S[j + 0], o0);
        S[j + 1] = fmaf(kk[j + 1], delta, S[j + 1]); o1 = fmaf(qq[j + 1], S[j + 1], o1);
        S[j + 2] = fmaf(kk[j + 2], delta, S[j + 2]); o2 = fmaf(qq[j + 2], S[j + 2], o2);
        S[j + 3] = fmaf(kk[j + 3], delta, S[j + 3]); o3 = fmaf(qq[j + 3], S[j + 3], o3);
    }
    float ov = (o0 + o1) + (o2 + o3);
    ov += __shfl_xor_sync(0xffffffffu, ov, 8);
    ov += __shfl_xor_sync(0xffffffffu, ov, 16);
    return ov;
}

__global__ void __launch_bounds__(256, 1)
kda_scan_kernel(const float* __restrict__ qg, const float* __restrict__ kg,
                const float* __restrict__ vg, const float* __restrict__ egg,
                const float* __restrict__ bg, float* __restrict__ og)
{
    const int h       = blockIdx.x;
    const int warp    = threadIdx.x >> 5;
    const int lane    = threadIdx.x & 31;
    const int quarter = lane >> 3;
    const int col     = (warp << 3) + (lane & 7);
    const int kb      = quarter << 4;

    const float* ep  = egg + h * DD + kb;
    const float* kp  = kg  + h * DD + kb;
    const float* qp  = qg  + h * DD + kb;
    const float* vpt = vg  + h * DD + col;
    const float* bpt = bg  + h;

    float S[16];
#pragma unroll
    for (int j = 0; j < 16; j++) S[j] = 0.f;

    const float* pf = nullptr;
    size_t pfstride = 0;
    if (warp == 0 && lane < 9) {
        if (lane < 8) {
            const float* bases[4] = {egg, kg, qg, vg};
            pf = bases[lane >> 1] + h * DD + (lane & 1) * 32;
            pfstride = PP;
        } else {
            pf = bg + h;
            pfstride = HH;
        }
    }

    float ea[16], ka[16], qa[16], va, ba;
    float eb[16], kbf[16], qb[16], vb, bb;

#define LOADSTAGE(E, KA, QA, V, B, t)                                            \
    do {                                                                         \
        size_t off = (size_t)(t) * PP;                                           \
        _Pragma("unroll")                                                        \
        for (int j = 0; j < 16; j += 4) {                                        \
            *reinterpret_cast<float4*>(&E[j])  =                                 \
                *reinterpret_cast<const float4*>(ep + off + j);                  \
            *reinterpret_cast<float4*>(&KA[j]) =                                 \
                *reinterpret_cast<const float4*>(kp + off + j);                  \
            *reinterpret_cast<float4*>(&QA[j]) =                                 \
                *reinterpret_cast<const float4*>(qp + off + j);                  \
        }                                                                        \
        V = vpt[off];                                                            \
        B = bpt[(size_t)(t) * HH];                                               \
    } while (0)

    LOADSTAGE(ea, ka, qa, va, ba, 0);
    LOADSTAGE(eb, kbf, qb, vb, bb, 1);

    for (int t = 0; t < TT; t += 2) {
        if (pf) {
            int tp = t + 8;
            if (tp + 1 < TT) {
                const float* p0 = pf + (size_t)tp * pfstride;
                const float* p1 = pf + (size_t)(tp + 1) * pfstride;
                asm volatile("prefetch.global.L2 [%0];" :: "l"(p0));
                asm volatile("prefetch.global.L2 [%0];" :: "l"(p1));
            }
        }
        float ov = kda_step(S, ea, ka, qa, va, ba);
        if (quarter == 0) og[(size_t)t * PP + h * DD + col] = ov;
        if (t + 2 < TT) LOADSTAGE(ea, ka, qa, va, ba, t + 2);

        ov = kda_step(S, eb, kbf, qb, vb, bb);
        if (quarter == 0) og[(size_t)(t + 1) * PP + h * DD + col] = ov;
        if (t + 3 < TT) LOADSTAGE(eb, kbf, qb, vb, bb, t + 3);
    }
#undef LOADSTAGE
}

// gated RMSNorm fused with bf16 hi/lo split for the O projection
__global__ void rms_gate_split_kernel(const float* __restrict__ o,
                                      const float* __restrict__ g2,
                                      const float* __restrict__ wn,
                                      __nv_bfloat16* __restrict__ hi,
                                      __nv_bfloat16* __restrict__ lo)
{
    const int t    = blockIdx.x;
    const int h    = blockIdx.y * 8 + (threadIdx.x >> 5);
    const int lane = threadIdx.x & 31;
    size_t base = (size_t)t * PP + h * DD;

    float a = o[base + lane];
    float b = o[base + lane + 32];
    float ss = a * a + b * b;
    ss += __shfl_xor_sync(0xffffffffu, ss, 16);
    ss += __shfl_xor_sync(0xffffffffu, ss, 8);
    ss += __shfl_xor_sync(0xffffffffu, ss, 4);
    ss += __shfl_xor_sync(0xffffffffu, ss, 2);
    ss += __shfl_xor_sync(0xffffffffu, ss, 1);
    float r = rsqrtf(ss * (1.f / 64.f) + 1e-5f);

    float ga = g2[base + lane];
    float gb = g2[base + lane + 32];
    float va = a * r * wn[lane]      * (1.f / (1.f + __expf(-ga)));
    float vb = b * r * wn[lane + 32] * (1.f / (1.f + __expf(-gb)));

    __nv_bfloat16 ha = __float2bfloat16(va);
    __nv_bfloat16 hb = __float2bfloat16(vb);
    hi[base + lane]      = ha;
    hi[base + lane + 32] = hb;
    lo[base + lane]      = __float2bfloat16(va - __bfloat162float(ha));
    lo[base + lane + 32] = __float2bfloat16(vb - __bfloat162float(hb));
}

// ---------------------------------------------------------------------------
// Host launcher
// ---------------------------------------------------------------------------
extern "C" void kernel_launch(void* const* d_in, const int* in_sizes, int n_in,
                              void* d_out, int out_size)
{
    const float* x    = (const float*)d_in[0];
    const float* Wq   = (const float*)d_in[1];
    const float* Wk   = (const float*)d_in[2];
    const float* Wv   = (const float*)d_in[3];
    const float* Wb   = (const float*)d_in[4];
    const float* Wfa  = (const float*)d_in[5];
    const float* Wfb  = (const float*)d_in[6];
    const float* dtb  = (const float*)d_in[7];
    const float* Alog = (const float*)d_in[8];
    const float* Wga  = (const float*)d_in[9];
    const float* Wgb  = (const float*)d_in[10];
    const float* cq   = (const float*)d_in[11];
    const float* ck   = (const float*)d_in[12];
    const float* cv   = (const float*)d_in[13];
    const float* wno  = (const float*)d_in[14];
    const float* Wo   = (const float*)d_in[15];
    float* out = (float*)d_out;

    static float *pxc = nullptr, *pq, *pk, *pv, *pgl, *pg2, *po,
                 *pfa, *pga, *pbl;
    static __nv_bfloat16 *pxhi, *pxlo, *pwch, *pwcl, *pwoth, *pwotl,
                         *pohi, *polo;
    if (!pxc) {
        cudaGetSymbolAddress((void**)&pxc, d_xc);
        cudaGetSymbolAddress((void**)&pq,  d_q);
        cudaGetSymbolAddress((void**)&pk,  d_k);
        cudaGetSymbolAddress((void**)&pv,  d_v);
        cudaGetSymbolAddress((void**)&pgl, d_gl);
        cudaGetSymbolAddress((void**)&pg2, d_g2);
        cudaGetSymbolAddress((void**)&po,  d_o);
        cudaGetSymbolAddress((void**)&pfa, d_fa);
        cudaGetSymbolAddress((void**)&pga, d_ga);
        cudaGetSymbolAddress((void**)&pbl, d_bl);
        cudaGetSymbolAddress((void**)&pxhi, d_xhi);
        cudaGetSymbolAddress((void**)&pxlo, d_xlo);
        cudaGetSymbolAddress((void**)&pwch, d_wch);
        cudaGetSymbolAddress((void**)&pwcl, d_wcl);
        cudaGetSymbolAddress((void**)&pwoth, d_woth);
        cudaGetSymbolAddress((void**)&pwotl, d_wotl);
        cudaGetSymbolAddress((void**)&pohi, d_ohi);
        cudaGetSymbolAddress((void**)&polo, d_olo);
        cudaFuncSetAttribute(mma_gemm_kernel,
                             cudaFuncAttributeMaxDynamicSharedMemorySize,
                             NSTAGE * STG_H * 2);
    }

    dim3 blk(256);
    const size_t smemMMA = NSTAGE * STG_H * 2;   // 81920 B

    // ---- prep: bf16 splits + weight transposes into combined W^T ----
    split_rows_kernel<<<2048, 256>>>(x, pxhi, pxlo, (size_t)TT * HIDD);
    transpose_split_kernel<<<dim3(PP / 32, HIDD / 32), dim3(32, 8)>>>(
        Wq, pwch + (size_t)0 * HIDD, pwcl + (size_t)0 * HIDD, HIDD, PP);
    transpose_split_kernel<<<dim3(PP / 32, HIDD / 32), dim3(32, 8)>>>(
        Wk, pwch + (size_t)2048 * HIDD, pwcl + (size_t)2048 * HIDD, HIDD, PP);
    transpose_split_kernel<<<dim3(PP / 32, HIDD / 32), dim3(32, 8)>>>(
        Wv, pwch + (size_t)4096 * HIDD, pwcl + (size_t)4096 * HIDD, HIDD, PP);
    pack_small_kernel<<<1024, 256>>>(Wfa, Wga, Wb,
                                     pwch + (size_t)6144 * HIDD,
                                     pwcl + (size_t)6144 * HIDD);
    transpose_split_kernel<<<dim3(HIDD / 32, PP / 32), dim3(32, 8)>>>(
        Wo, pwoth, pwotl, PP, HIDD);

    // ---- ONE combined projection GEMM: [T,HID] @ [HID, 6400] ----
    mma_gemm_kernel<<<dim3(NCMB / 128, TT / 128), blk, smemMMA>>>(
        pxhi, pxhi, pxlo, pwch, pwcl, pwch, pxc, HIDD, NCMB);

    extract_small_kernel<<<1024, 256>>>(pxc, pfa, pga, pbl);

    // ---- low-rank expansions (K=64, SIMT) ----
    dim3 gExp(PP / 128, TT / 128);
    sgemm_kernel<128, 128, 16, 8, 8><<<gExp, blk>>>(pfa, Wfb, pgl, TT, PP, DD);
    sgemm_kernel<128, 128, 16, 8, 8><<<gExp, blk>>>(pga, Wgb, pg2, TT, PP, DD);

    // ---- elementwise / scan ----
    decay_kernel<<<4096, 256>>>(pgl, dtb, Alog);
    dim3 cgrid(TT, HH / 8);
    conv_silu_kernel<<<cgrid, blk>>>(pxc + 0,    NCMB, cq, pq, 2);
    conv_silu_kernel<<<cgrid, blk>>>(pxc + 2048, NCMB, ck, pk, 1);
    conv_silu_kernel<<<cgrid, blk>>>(pxc + 4096, NCMB, cv, pv, 0);
    kda_scan_kernel<<<HH, 256>>>(pq, pk, pv, pgl, pbl, po);
    rms_gate_split_kernel<<<cgrid, blk>>>(po, pg2, wno, pohi, polo);

    // ---- output projection on tensor cores ----
    mma_gemm_kernel<<<dim3(HIDD / 128, TT / 128), blk, smemMMA>>>(
        pohi, pohi, polo, pwoth, pwotl, pwoth, out, PP, HIDD);

    (void)in_sizes; (void)n_in; (void)out_size;
}

// round 6
// speedup vs baseline: 2.4898x; 1.0346x over previous
#include <cuda_runtime.h>
#include <cuda_bf16.h>
#include <cstdint>

// ---------------------------------------------------------------------------
// Problem constants
// ---------------------------------------------------------------------------
#define TT   4096
#define HIDD 4096
#define HH   32
#define DD   64
#define PP   2048
#define NCMB 6400        // combined QKV+small output columns: 3*2048 + 256
#define NGE  4096        // combined gl|g2 expansion columns

// ---------------------------------------------------------------------------
// Device scratch
// ---------------------------------------------------------------------------
__device__ float d_xc[TT * NCMB];        // combined qkv|small projection out
__device__ float d_ge[TT * NGE];         // combined gl|g2 expansion out
__device__ float d_q [TT * PP];
__device__ float d_k [TT * PP];
__device__ float d_v [TT * PP];
__device__ float d_bl[TT * HH];

__device__ __nv_bfloat16 d_xhi[TT * HIDD], d_xlo[TT * HIDD];
__device__ __nv_bfloat16 d_wch[(size_t)NCMB * HIDD], d_wcl[(size_t)NCMB * HIDD];
__device__ __nv_bfloat16 d_woth[HIDD * PP], d_wotl[HIDD * PP];
__device__ __nv_bfloat16 d_ohi[TT * PP],  d_olo[TT * PP];
__device__ __nv_bfloat16 d_aghi[TT * 128], d_aglo[TT * 128];   // [fa|ga] bf16
__device__ __nv_bfloat16 d_wgeh[NGE * 128], d_wgel[NGE * 128]; // blockdiag W^T

// ---------------------------------------------------------------------------
// cp.async / ldmatrix / mma helpers
// ---------------------------------------------------------------------------
__device__ __forceinline__ uint32_t smem_u32(const void* p) {
    uint32_t a;
    asm("{ .reg .u64 t; cvta.to.shared.u64 t, %1; cvt.u32.u64 %0, t; }"
        : "=r"(a) : "l"(p));
    return a;
}
#define CP_ASYNC16(smem, gptr) \
    asm volatile("cp.async.cg.shared.global [%0], [%1], 16;\n" \
                 :: "r"(smem), "l"(gptr))
#define CP_COMMIT() asm volatile("cp.async.commit_group;\n" ::: "memory")
#define CP_WAIT1()  asm volatile("cp.async.wait_group 1;\n" ::: "memory")
#define CP_WAIT0()  asm volatile("cp.async.wait_group 0;\n" ::: "memory")

#define LDMX4(r0, r1, r2, r3, addr)                                       \
    asm volatile("ldmatrix.sync.aligned.m8n8.x4.shared.b16 "              \
                 "{%0, %1, %2, %3}, [%4];"                                \
                 : "=r"(r0), "=r"(r1), "=r"(r2), "=r"(r3) : "r"(addr))

#define MMA16816(c0, c1, c2, c3, a0, a1, a2, a3, b0, b1)                  \
    asm volatile("mma.sync.aligned.m16n8k16.row.col.f32.bf16.bf16.f32 "   \
                 "{%0, %1, %2, %3}, {%4, %5, %6, %7}, {%8, %9}, "         \
                 "{%0, %1, %2, %3};"                                      \
                 : "+f"(c0), "+f"(c1), "+f"(c2), "+f"(c3)                 \
                 : "r"(a0), "r"(a1), "r"(a2), "r"(a3), "r"(b0), "r"(b1))

// ---------------------------------------------------------------------------
// bf16 HMMA GEMM, 3-pass split:  C = A0@B0 + A1@B1 + A2@B2  (fp32 out)
// A*: [M,K] bf16 row-major.  B*: [N,K] bf16 row-major (W^T).
// Block 128x128, BK=64, 8 warps (2x4), warp tile 64x32.
// 3-stage cp.async pipeline, ONE __syncthreads per 64-wide K-chunk.
// ---------------------------------------------------------------------------
#define BKH     72                      // 64 halves + 8 pad (144 B rows)
#define STG_H   (2 * 128 * BKH)         // halves per stage (A then B)
#define NSTAGE  3

__global__ void __launch_bounds__(256, 2)
mma_gemm_kernel(const __nv_bfloat16* __restrict__ A0, const __nv_bfloat16* __restrict__ A1,
                const __nv_bfloat16* __restrict__ A2,
                const __nv_bfloat16* __restrict__ B0, const __nv_bfloat16* __restrict__ B1,
                const __nv_bfloat16* __restrict__ B2,
                float* __restrict__ C, int K, int ldc)
{
    extern __shared__ __align__(16) __nv_bfloat16 smem[];
    const uint32_t sbase = smem_u32(smem);

    const int tid   = threadIdx.x;
    const int wid   = tid >> 5;
    const int lane  = tid & 31;
    const int warpM = wid >> 2;          // 0..1
    const int warpN = wid & 3;           // 0..3
    const int rowBase = blockIdx.y * 128;
    const int colBase = blockIdx.x * 128;

    const __nv_bfloat16* APs[3] = {A0, A1, A2};
    const __nv_bfloat16* BPs[3] = {B0, B1, B2};
    const int kChunks = K >> 6;          // K/64
    const int nIter   = 3 * kChunks;

    float acc[4][4][4];
#pragma unroll
    for (int i = 0; i < 4; i++)
#pragma unroll
        for (int j = 0; j < 4; j++)
#pragma unroll
            for (int r = 0; r < 4; r++) acc[i][j][r] = 0.f;

    const int ldr  = tid >> 3;           // 0..31
    const int ldc8 = (tid & 7) * 8;      // 0..56 step 8

#define LOAD_STAGE(j, s)                                                        \
    do {                                                                        \
        int _pass = (j) / kChunks;                                              \
        int _kOff = ((j) - _pass * kChunks) << 6;                               \
        const __nv_bfloat16* _Ap = APs[_pass];                                  \
        const __nv_bfloat16* _Bp = BPs[_pass];                                  \
        uint32_t _sA = sbase + (uint32_t)(s) * (STG_H * 2);                     \
        uint32_t _sB = _sA + 128 * BKH * 2;                                     \
        _Pragma("unroll")                                                       \
        for (int _i = 0; _i < 4; _i++) {                                        \
            int _r = ldr + _i * 32;                                             \
            CP_ASYNC16(_sA + (_r * BKH + ldc8) * 2,                             \
                       _Ap + (size_t)(rowBase + _r) * K + _kOff + ldc8);        \
        }                                                                       \
        _Pragma("unroll")                                                       \
        for (int _i = 0; _i < 4; _i++) {                                        \
            int _r = ldr + _i * 32;                                             \
            CP_ASYNC16(_sB + (_r * BKH + ldc8) * 2,                             \
                       _Bp + (size_t)(colBase + _r) * K + _kOff + ldc8);        \
        }                                                                       \
        CP_COMMIT();                                                            \
    } while (0)

    LOAD_STAGE(0, 0);
    LOAD_STAGE(1, 1);

    const int aRow = (lane & 15);
    const int aKof = (lane >> 4) * 8;
    const int bNof = ((lane >> 4) & 1) * 8 + (lane & 7);
    const int bKof = ((lane >> 3) & 1) * 8;

    int s = 0;
    for (int it = 0; it < nIter; it++) {
        CP_WAIT1();
        __syncthreads();
        // stage (s+2)%3 was computed in iteration it-1; barrier above protects it.
        int jn = it + 2;
        if (jn < nIter) {
            int sn = s + 2; if (sn >= NSTAGE) sn -= NSTAGE;
            LOAD_STAGE(jn, sn);
        } else {
            CP_COMMIT();     // keep group accounting aligned with CP_WAIT1
        }

        uint32_t aBase = sbase + (uint32_t)s * (STG_H * 2) +
                         (warpM * 64) * (BKH * 2);
        uint32_t bBase = sbase + (uint32_t)s * (STG_H * 2) + 128 * BKH * 2 +
                         (warpN * 32) * (BKH * 2);

#pragma unroll
        for (int kk = 0; kk < 4; kk++) {
            uint32_t a[4][4];
            uint32_t b[2][4];
#pragma unroll
            for (int mi = 0; mi < 4; mi++) {
                uint32_t ad = aBase + ((mi * 16 + aRow) * BKH + kk * 16 + aKof) * 2;
                LDMX4(a[mi][0], a[mi][1], a[mi][2], a[mi][3], ad);
            }
#pragma unroll
            for (int nb = 0; nb < 2; nb++) {
                uint32_t bd = bBase + ((nb * 16 + bNof) * BKH + kk * 16 + bKof) * 2;
                LDMX4(b[nb][0], b[nb][1], b[nb][2], b[nb][3], bd);
            }
#pragma unroll
            for (int mi = 0; mi < 4; mi++) {
#pragma unroll
                for (int ni = 0; ni < 4; ni++) {
                    int nb = ni >> 1;
                    int hi = (ni & 1) * 2;
                    MMA16816(acc[mi][ni][0], acc[mi][ni][1],
                             acc[mi][ni][2], acc[mi][ni][3],
                             a[mi][0], a[mi][1], a[mi][2], a[mi][3],
                             b[nb][hi], b[nb][hi + 1]);
                }
            }
        }
        if (++s == NSTAGE) s = 0;
    }
    CP_WAIT0();

    const int erow = rowBase + warpM * 64 + (lane >> 2);
    const int ecol = colBase + warpN * 32 + (lane & 3) * 2;
#pragma unroll
    for (int mi = 0; mi < 4; mi++) {
#pragma unroll
        for (int ni = 0; ni < 4; ni++) {
            float* p0 = C + (size_t)(erow + mi * 16) * ldc + ecol + ni * 8;
            float* p1 = p0 + 8 * (size_t)ldc;
            *reinterpret_cast<float2*>(p0) = make_float2(acc[mi][ni][0], acc[mi][ni][1]);
            *reinterpret_cast<float2*>(p1) = make_float2(acc[mi][ni][2], acc[mi][ni][3]);
        }
    }
}

// ---------------------------------------------------------------------------
// Prep kernels
// ---------------------------------------------------------------------------
__global__ void split_rows_kernel(const float* __restrict__ x,
                                  __nv_bfloat16* __restrict__ hi,
                                  __nv_bfloat16* __restrict__ lo, size_t n)
{
    for (size_t i = (size_t)blockIdx.x * blockDim.x + threadIdx.x; i < n;
         i += (size_t)gridDim.x * blockDim.x) {
        float v = x[i];
        __nv_bfloat16 h = __float2bfloat16(v);
        hi[i] = h;
        lo[i] = __float2bfloat16(v - __bfloat162float(h));
    }
}

// in [R, C] fp32 -> out hi/lo [C, R] bf16
__global__ void transpose_split_kernel(const float* __restrict__ in,
                                       __nv_bfloat16* __restrict__ hi,
                                       __nv_bfloat16* __restrict__ lo,
                                       int R, int C)
{
    __shared__ float t[32][33];
    int c0 = blockIdx.x * 32, r0 = blockIdx.y * 32;
    int x = threadIdx.x, y = threadIdx.y;
#pragma unroll
    for (int i = 0; i < 32; i += 8)
        t[y + i][x] = in[(size_t)(r0 + y + i) * C + c0 + x];
    __syncthreads();
#pragma unroll
    for (int i = 0; i < 32; i += 8) {
        float v = t[x][y + i];
        __nv_bfloat16 h = __float2bfloat16(v);
        size_t idx = (size_t)(c0 + y + i) * R + r0 + x;
        hi[idx] = h;
        lo[idx] = __float2bfloat16(v - __bfloat162float(h));
    }
}

// pack Wfa[HID,64] | Wga[HID,64] | Wb[HID,32] -> W^T [256, HID] (zero pad)
__global__ void pack_small_kernel(const float* __restrict__ Wfa,
                                  const float* __restrict__ Wga,
                                  const float* __restrict__ Wb,
                                  __nv_bfloat16* __restrict__ hi,
                                  __nv_bfloat16* __restrict__ lo)
{
    size_t total = (size_t)256 * HIDD;
    for (size_t i = (size_t)blockIdx.x * blockDim.x + threadIdx.x; i < total;
         i += (size_t)gridDim.x * blockDim.x) {
        int n = (int)(i / HIDD);
        int k = (int)(i % HIDD);
        float v = 0.f;
        if (n < 64)       v = Wfa[(size_t)k * 64 + n];
        else if (n < 128) v = Wga[(size_t)k * 64 + (n - 64)];
        else if (n < 160) v = Wb[(size_t)k * 32 + (n - 128)];
        __nv_bfloat16 h = __float2bfloat16(v);
        hi[i] = h;
        lo[i] = __float2bfloat16(v - __bfloat162float(h));
    }
}

// pack block-diagonal expansion weights: W^T [NGE=4096, 128]
// rows 0..2047:   Wfb^T (Wfb[k][n], k<64) in cols 0..63, zeros 64..127
// rows 2048..4095: Wgb^T in cols 64..127, zeros 0..63
__global__ void pack_ge_kernel(const float* __restrict__ Wfb,
                               const float* __restrict__ Wgb,
                               __nv_bfloat16* __restrict__ hi,
                               __nv_bfloat16* __restrict__ lo)
{
    size_t total = (size_t)NGE * 128;
    for (size_t i = (size_t)blockIdx.x * blockDim.x + threadIdx.x; i < total;
         i += (size_t)gridDim.x * blockDim.x) {
        int n = (int)(i >> 7);
        int k = (int)(i & 127);
        float v = 0.f;
        if (n < 2048) {
            if (k < 64) v = Wfb[(size_t)k * PP + n];
        } else {
            if (k >= 64) v = Wgb[(size_t)(k - 64) * PP + (n - 2048)];
        }
        __nv_bfloat16 h = __float2bfloat16(v);
        hi[i] = h;
        lo[i] = __float2bfloat16(v - __bfloat162float(h));
    }
}

// extract fa|ga (bf16 split, packed [T,128]) + beta from combined GEMM out
__global__ void extract_small_kernel(const float* __restrict__ xc,
                                     __nv_bfloat16* __restrict__ aghi,
                                     __nv_bfloat16* __restrict__ aglo,
                                     float* __restrict__ bl)
{
    size_t total = (size_t)TT * 160;
    for (size_t i = (size_t)blockIdx.x * blockDim.x + threadIdx.x; i < total;
         i += (size_t)gridDim.x * blockDim.x) {
        int m = (int)(i / 160);
        int c = (int)(i % 160);
        float v = xc[(size_t)m * NCMB + 6144 + c];
        if (c < 128) {
            __nv_bfloat16 h = __float2bfloat16(v);
            aghi[(size_t)m * 128 + c] = h;
            aglo[(size_t)m * 128 + c] = __float2bfloat16(v - __bfloat162float(h));
        } else {
            bl[(size_t)m * 32 + (c - 128)] = v;
        }
    }
}

// ---------------------------------------------------------------------------
// conv+silu (+l2norm) — x has row stride ldx (combined buffer)
// ---------------------------------------------------------------------------
__global__ void conv_silu_kernel(const float* __restrict__ x, int ldx,
                                 const float* __restrict__ w,
                                 float* __restrict__ y, int mode)
{
    const int t    = blockIdx.x;
    const int h    = blockIdx.y * 8 + (threadIdx.x >> 5);
    const int lane = threadIdx.x & 31;

    float val[2];
    float ss = 0.f;
#pragma unroll
    for (int e = 0; e < 2; e++) {
        int d = lane + e * 32;
        int p = h * DD + d;
        const float* xp = x + p;
        float w0 = w[p * 4 + 0], w1 = w[p * 4 + 1];
        float w2 = w[p * 4 + 2], w3 = w[p * 4 + 3];
        float acc = xp[(size_t)t * ldx] * w3;
        if (t >= 1) acc = fmaf(xp[(size_t)(t - 1) * ldx], w2, acc);
        if (t >= 2) acc = fmaf(xp[(size_t)(t - 2) * ldx], w1, acc);
        if (t >= 3) acc = fmaf(xp[(size_t)(t - 3) * ldx], w0, acc);
        float sv = acc / (1.f + __expf(-acc));
        val[e] = sv;
        ss += sv * sv;
    }
    if (mode > 0) {
        ss += __shfl_xor_sync(0xffffffffu, ss, 16);
        ss += __shfl_xor_sync(0xffffffffu, ss, 8);
        ss += __shfl_xor_sync(0xffffffffu, ss, 4);
        ss += __shfl_xor_sync(0xffffffffu, ss, 2);
        ss += __shfl_xor_sync(0xffffffffu, ss, 1);
        float r = rsqrtf(ss + 1e-6f);
        if (mode == 2) r *= 0.125f;
        val[0] *= r; val[1] *= r;
    }
    size_t base = (size_t)t * PP + h * DD;
    y[base + lane]      = val[0];
    y[base + lane + 32] = val[1];
}

// decay on gl view inside d_ge (cols 0..2047, row stride NGE), in place
__global__ void decay_kernel(float* __restrict__ ge,
                             const float* __restrict__ dtb,
                             const float* __restrict__ Alog)
{
    const size_t total = (size_t)TT * PP;
    for (size_t idx = (size_t)blockIdx.x * blockDim.x + threadIdx.x;
         idx < total; idx += (size_t)gridDim.x * blockDim.x) {
        int pr  = (int)(idx & (PP - 1));
        size_t row = idx >> 11;
        int h   = pr >> 6;
        size_t a = row * NGE + pr;
        float xv = ge[a] + dtb[pr];
        float sp = (xv > 20.f) ? xv : log1pf(expf(xv));
        ge[a] = expf(-expf(Alog[h]) * sp);
    }
}

__device__ __forceinline__ float kda_step(float S[16],
                                          const float eg[16], const float kk[16],
                                          const float qq[16], float vv, float braw)
{
    float vp0 = 0.f, vp1 = 0.f, vp2 = 0.f, vp3 = 0.f;
#pragma unroll
    for (int j = 0; j < 16; j += 4) {
        float s0 = S[j + 0] * eg[j + 0]; S[j + 0] = s0; vp0 = fmaf(kk[j + 0], s0, vp0);
        float s1 = S[j + 1] * eg[j + 1]; S[j + 1] = s1; vp1 = fmaf(kk[j + 1], s1, vp1);
        float s2 = S[j + 2] * eg[j + 2]; S[j + 2] = s2; vp2 = fmaf(kk[j + 2], s2, vp2);
        float s3 = S[j + 3] * eg[j + 3]; S[j + 3] = s3; vp3 = fmaf(kk[j + 3], s3, vp3);
    }
    float vpred = (vp0 + vp1) + (vp2 + vp3);
    vpred += __shfl_xor_sync(0xffffffffu, vpred, 8);
    vpred += __shfl_xor_sync(0xffffffffu, vpred, 16);
    float b = 1.f / (1.f + __expf(-braw));
    float delta = (vv - vpred) * b;
    float o0 = 0.f, o1 = 0.f, o2 = 0.f, o3 = 0.f;
#pragma unroll
    for (int j = 0; j < 16; j += 4) {
        S[j + 0] = fmaf(kk[j + 0], delta, S[j + 0]); o0 = fmaf(qq[j + 0], S[j + 0], o0);
        S[j + 1] = fmaf(kk[j + 1], delta, S[j + 1]); o1 = fmaf(qq[j + 1], S[j + 1], o1);
        S[j + 2] = fmaf(kk[j + 2], delta, S[j + 2]); o2 = fmaf(qq[j + 2], S[j + 2], o2);
        S[j + 3] = fmaf(kk[j + 3], delta, S[j + 3]); o3 = fmaf(qq[j + 3], S[j + 3], o3);
    }
    float ov = (o0 + o1) + (o2 + o3);
    ov += __shfl_xor_sync(0xffffffffu, ov, 8);
    ov += __shfl_xor_sync(0xffffffffu, ov, 16);
    return ov;
}

// egg has row stride NGE (view into combined buffer); q/k/v stride PP
__global__ void __launch_bounds__(256, 1)
kda_scan_kernel(const float* __restrict__ qg, const float* __restrict__ kg,
                const float* __restrict__ vg, const float* __restrict__ egg,
                const float* __restrict__ bg, float* __restrict__ og)
{
    const int h       = blockIdx.x;
    const int warp    = threadIdx.x >> 5;
    const int lane    = threadIdx.x & 31;
    const int quarter = lane >> 3;
    const int col     = (warp << 3) + (lane & 7);
    const int kb      = quarter << 4;

    const float* ep  = egg + h * DD + kb;
    const float* kp  = kg  + h * DD + kb;
    const float* qp  = qg  + h * DD + kb;
    const float* vpt = vg  + h * DD + col;
    const float* bpt = bg  + h;

    float S[16];
#pragma unroll
    for (int j = 0; j < 16; j++) S[j] = 0.f;

    const float* pf = nullptr;
    size_t pfstride = 0;
    if (warp == 0 && lane < 9) {
        if (lane < 8) {
            const float* bases[4] = {egg, kg, qg, vg};
            const size_t strides[4] = {NGE, PP, PP, PP};
            pf = bases[lane >> 1] + h * DD + (lane & 1) * 32;
            pfstride = strides[lane >> 1];
        } else {
            pf = bg + h;
            pfstride = HH;
        }
    }

    float ea[16], ka[16], qa[16], va, ba;
    float eb[16], kbf[16], qb[16], vb, bb;

#define LOADSTAGE(E, KA, QA, V, B, t)                                            \
    do {                                                                         \
        size_t offe = (size_t)(t) * NGE;                                         \
        size_t off  = (size_t)(t) * PP;                                          \
        _Pragma("unroll")                                                        \
        for (int j = 0; j < 16; j += 4) {                                        \
            *reinterpret_cast<float4*>(&E[j])  =                                 \
                *reinterpret_cast<const float4*>(ep + offe + j);                 \
            *reinterpret_cast<float4*>(&KA[j]) =                                 \
                *reinterpret_cast<const float4*>(kp + off + j);                  \
            *reinterpret_cast<float4*>(&QA[j]) =                                 \
                *reinterpret_cast<const float4*>(qp + off + j);                  \
        }                                                                        \
        V = vpt[off];                                                            \
        B = bpt[(size_t)(t) * HH];                                               \
    } while (0)

    LOADSTAGE(ea, ka, qa, va, ba, 0);
    LOADSTAGE(eb, kbf, qb, vb, bb, 1);

    for (int t = 0; t < TT; t += 2) {
        if (pf) {
            int tp = t + 8;
            if (tp + 1 < TT) {
                const float* p0 = pf + (size_t)tp * pfstride;
                const float* p1 = pf + (size_t)(tp + 1) * pfstride;
                asm volatile("prefetch.global.L2 [%0];" :: "l"(p0));
                asm volatile("prefetch.global.L2 [%0];" :: "l"(p1));
            }
        }
        float ov = kda_step(S, ea, ka, qa, va, ba);
        if (quarter == 0) og[(size_t)t * PP + h * DD + col] = ov;
        if (t + 2 < TT) LOADSTAGE(ea, ka, qa, va, ba, t + 2);

        ov = kda_step(S, eb, kbf, qb, vb, bb);
        if (quarter == 0) og[(size_t)(t + 1) * PP + h * DD + col] = ov;
        if (t + 3 < TT) LOADSTAGE(eb, kbf, qb, vb, bb, t + 3);
    }
#undef LOADSTAGE
}

// gated RMSNorm fused with bf16 hi/lo split; g2 is a strided view (ld = NGE)
__global__ void rms_gate_split_kernel(const float* __restrict__ o,
                                      const float* __restrict__ g2, int ldg,
                                      const float* __restrict__ wn,
                                      __nv_bfloat16* __restrict__ hi,
                                      __nv_bfloat16* __restrict__ lo)
{
    const int t    = blockIdx.x;
    const int h    = blockIdx.y * 8 + (threadIdx.x >> 5);
    const int lane = threadIdx.x & 31;
    size_t base  = (size_t)t * PP + h * DD;
    size_t gbase = (size_t)t * ldg + h * DD;

    float a = o[base + lane];
    float b = o[base + lane + 32];
    float ss = a * a + b * b;
    ss += __shfl_xor_sync(0xffffffffu, ss, 16);
    ss += __shfl_xor_sync(0xffffffffu, ss, 8);
    ss += __shfl_xor_sync(0xffffffffu, ss, 4);
    ss += __shfl_xor_sync(0xffffffffu, ss, 2);
    ss += __shfl_xor_sync(0xffffffffu, ss, 1);
    float r = rsqrtf(ss * (1.f / 64.f) + 1e-5f);

    float ga = g2[gbase + lane];
    float gb = g2[gbase + lane + 32];
    float va = a * r * wn[lane]      * (1.f / (1.f + __expf(-ga)));
    float vb = b * r * wn[lane + 32] * (1.f / (1.f + __expf(-gb)));

    __nv_bfloat16 ha = __float2bfloat16(va);
    __nv_bfloat16 hb = __float2bfloat16(vb);
    hi[base + lane]      = ha;
    hi[base + lane + 32] = hb;
    lo[base + lane]      = __float2bfloat16(va - __bfloat162float(ha));
    lo[base + lane + 32] = __float2bfloat16(vb - __bfloat162float(hb));
}

// ---------------------------------------------------------------------------
// Host launcher
// ---------------------------------------------------------------------------
extern "C" void kernel_launch(void* const* d_in, const int* in_sizes, int n_in,
                              void* d_out, int out_size)
{
    const float* x    = (const float*)d_in[0];
    const float* Wq   = (const float*)d_in[1];
    const float* Wk   = (const float*)d_in[2];
    const float* Wv   = (const float*)d_in[3];
    const float* Wb   = (const float*)d_in[4];
    const float* Wfa  = (const float*)d_in[5];
    const float* Wfb  = (const float*)d_in[6];
    const float* dtb  = (const float*)d_in[7];
    const float* Alog = (const float*)d_in[8];
    const float* Wga  = (const float*)d_in[9];
    const float* Wgb  = (const float*)d_in[10];
    const float* cq   = (const float*)d_in[11];
    const float* ck   = (const float*)d_in[12];
    const float* cv   = (const float*)d_in[13];
    const float* wno  = (const float*)d_in[14];
    const float* Wo   = (const float*)d_in[15];
    float* out = (float*)d_out;

    static float *pxc = nullptr, *pge, *pq, *pk, *pv, *pbl;
    static __nv_bfloat16 *pxhi, *pxlo, *pwch, *pwcl, *pwoth, *pwotl,
                         *pohi, *polo, *paghi, *paglo, *pwgeh, *pwgel;
    if (!pxc) {
        cudaGetSymbolAddress((void**)&pxc, d_xc);
        cudaGetSymbolAddress((void**)&pge, d_ge);
        cudaGetSymbolAddress((void**)&pq,  d_q);
        cudaGetSymbolAddress((void**)&pk,  d_k);
        cudaGetSymbolAddress((void**)&pv,  d_v);
        cudaGetSymbolAddress((void**)&pbl, d_bl);
        cudaGetSymbolAddress((void**)&pxhi, d_xhi);
        cudaGetSymbolAddress((void**)&pxlo, d_xlo);
        cudaGetSymbolAddress((void**)&pwch, d_wch);
        cudaGetSymbolAddress((void**)&pwcl, d_wcl);
        cudaGetSymbolAddress((void**)&pwoth, d_woth);
        cudaGetSymbolAddress((void**)&pwotl, d_wotl);
        cudaGetSymbolAddress((void**)&pohi, d_ohi);
        cudaGetSymbolAddress((void**)&polo, d_olo);
        cudaGetSymbolAddress((void**)&paghi, d_aghi);
        cudaGetSymbolAddress((void**)&paglo, d_aglo);
        cudaGetSymbolAddress((void**)&pwgeh, d_wgeh);
        cudaGetSymbolAddress((void**)&pwgel, d_wgel);
        cudaFuncSetAttribute(mma_gemm_kernel,
                             cudaFuncAttributeMaxDynamicSharedMemorySize,
                             NSTAGE * STG_H * 2);
    }

    dim3 blk(256);
    const size_t smemMMA = NSTAGE * STG_H * 2;   // 110592 B

    // ---- prep: bf16 splits + weight transposes into combined W^T ----
    split_rows_kernel<<<2048, 256>>>(x, pxhi, pxlo, (size_t)TT * HIDD);
    transpose_split_kernel<<<dim3(PP / 32, HIDD / 32), dim3(32, 8)>>>(
        Wq, pwch + (size_t)0 * HIDD, pwcl + (size_t)0 * HIDD, HIDD, PP);
    transpose_split_kernel<<<dim3(PP / 32, HIDD / 32), dim3(32, 8)>>>(
        Wk, pwch + (size_t)2048 * HIDD, pwcl + (size_t)2048 * HIDD, HIDD, PP);
    transpose_split_kernel<<<dim3(PP / 32, HIDD / 32), dim3(32, 8)>>>(
        Wv, pwch + (size_t)4096 * HIDD, pwcl + (size_t)4096 * HIDD, HIDD, PP);
    pack_small_kernel<<<1024, 256>>>(Wfa, Wga, Wb,
                                     pwch + (size_t)6144 * HIDD,
                                     pwcl + (size_t)6144 * HIDD);
    transpose_split_kernel<<<dim3(HIDD / 32, PP / 32), dim3(32, 8)>>>(
        Wo, pwoth, pwotl, PP, HIDD);
    pack_ge_kernel<<<512, 256>>>(Wfb, Wgb, pwgeh, pwgel);

    // ---- ONE combined projection GEMM: [T,HID] @ [HID, 6400] ----
    mma_gemm_kernel<<<dim3(NCMB / 128, TT / 128), blk, smemMMA>>>(
        pxhi, pxhi, pxlo, pwch, pwcl, pwch, pxc, HIDD, NCMB);

    extract_small_kernel<<<1024, 256>>>(pxc, paghi, paglo, pbl);

    // ---- combined gl|g2 expansion GEMM: [T,128] @ [128, 4096] ----
    mma_gemm_kernel<<<dim3(NGE / 128, TT / 128), blk, smemMMA>>>(
        paghi, paghi, paglo, pwgeh, pwgel, pwgeh, pge, 128, NGE);

    // ---- elementwise / scan ----
    decay_kernel<<<4096, 256>>>(pge, dtb, Alog);
    dim3 cgrid(TT, HH / 8);
    conv_silu_kernel<<<cgrid, blk>>>(pxc + 0,    NCMB, cq, pq, 2);
    conv_silu_kernel<<<cgrid, blk>>>(pxc + 2048, NCMB, ck, pk, 1);
    conv_silu_kernel<<<cgrid, blk>>>(pxc + 4096, NCMB, cv, pv, 0);
    kda_scan_kernel<<<HH, 256>>>(pq, pk, pv, pge, pbl, pq /* reuse as o */);
    rms_gate_split_kernel<<<cgrid, blk>>>(pq, pge + 2048, NGE, wno, pohi, polo);

    // ---- output projection on tensor cores ----
    mma_gemm_kernel<<<dim3(HIDD / 128, TT / 128), blk, smemMMA>>>(
        pohi, pohi, polo, pwoth, pwotl, pwoth, out, PP, HIDD);

    (void)in_sizes; (void)n_in; (void)out_size;
}

// round 10
// speedup vs baseline: 3.0620x; 1.2298x over previous
#include <cuda_runtime.h>
#include <cuda_fp16.h>
#include <cstdint>

// ---------------------------------------------------------------------------
// Problem constants
// ---------------------------------------------------------------------------
#define TT   4096
#define HIDD 4096
#define HH   32
#define DD   64
#define PP   2048
#define NCMB 6400        // combined QKV+small output columns: 3*2048 + 256
#define NGE  4096        // combined gl|g2 expansion columns
#define K1   (2 * HIDD)  // 8192 : doubled-K for projection GEMM
#define K2   256         // doubled-K for ge expansion (2*128)
#define K3   (2 * PP)    // 4096 : doubled-K for O projection

// ---------------------------------------------------------------------------
// Device scratch
// ---------------------------------------------------------------------------
__device__ float d_xc[TT * NCMB];        // combined qkv|small projection out
__device__ float d_ge[TT * NGE];         // combined gl|g2 expansion out
__device__ float d_q [TT * PP];
__device__ float d_k [TT * PP];
__device__ float d_v [TT * PP];
__device__ float d_bl[TT * HH];

__device__ __half d_xs [(size_t)TT * K1];    // A: [xhi | xlo] fp16 along K
__device__ __half d_wcs[(size_t)NCMB * K1];  // B: combined W^T [hi | hi]
__device__ __half d_wos[(size_t)HIDD * K3];  // B: Wo^T [hi | hi]
__device__ __half d_os [(size_t)TT * K3];    // A: gated o [hi | lo]
__device__ __half d_ags[(size_t)TT * K2];    // A: [fa|ga] [hi | lo]
__device__ __half d_wges[(size_t)NGE * K2];  // B: blockdiag exp W^T [hi | hi]

// ---------------------------------------------------------------------------
// cp.async / ldmatrix / mma helpers
// ---------------------------------------------------------------------------
__device__ __forceinline__ uint32_t smem_u32(const void* p) {
    uint32_t a;
    asm("{ .reg .u64 t; cvta.to.shared.u64 t, %1; cvt.u32.u64 %0, t; }"
        : "=r"(a) : "l"(p));
    return a;
}
#define CP_ASYNC16(smem, gptr) \
    asm volatile("cp.async.cg.shared.global [%0], [%1], 16;\n" \
                 :: "r"(smem), "l"(gptr))
#define CP_COMMIT() asm volatile("cp.async.commit_group;\n" ::: "memory")
#define CP_WAIT1()  asm volatile("cp.async.wait_group 1;\n" ::: "memory")
#define CP_WAIT0()  asm volatile("cp.async.wait_group 0;\n" ::: "memory")

#define LDMX4(r0, r1, r2, r3, addr)                                       \
    asm volatile("ldmatrix.sync.aligned.m8n8.x4.shared.b16 "              \
                 "{%0, %1, %2, %3}, [%4];"                                \
                 : "=r"(r0), "=r"(r1), "=r"(r2), "=r"(r3) : "r"(addr))

#define MMA16816(c0, c1, c2, c3, a0, a1, a2, a3, b0, b1)                  \
    asm volatile("mma.sync.aligned.m16n8k16.row.col.f32.f16.f16.f32 "     \
                 "{%0, %1, %2, %3}, {%4, %5, %6, %7}, {%8, %9}, "         \
                 "{%0, %1, %2, %3};"                                      \
                 : "+f"(c0), "+f"(c1), "+f"(c2), "+f"(c3)                 \
                 : "r"(a0), "r"(a1), "r"(a2), "r"(a3), "r"(b0), "r"(b1))

// ---------------------------------------------------------------------------
// fp16 HMMA GEMM over doubled-K inputs:  C = A @ B^T  (fp32 accum/out)
// A: [M,K] fp16 row-major = [Ahi | Alo].  B: [N,K] fp16 = [Bhi | Bhi].
// Result = (Ahi + Alo) @ Bhi^T : A at ~22-bit precision, B at fp16.
// Block 128x128, BK=64, 8 warps (2x4), warp tile 64x32.
// 3-stage cp.async pipeline, ONE __syncthreads per 64-wide K-chunk.
// ---------------------------------------------------------------------------
#define BKH     72                      // 64 halves + 8 pad (144 B rows)
#define STG_H   (2 * 128 * BKH)         // halves per stage (A then B)
#define NSTAGE  3

__global__ void __launch_bounds__(256, 2)
mma_gemm_kernel(const __half* __restrict__ A,
                const __half* __restrict__ B,
                float* __restrict__ C, int K, int ldc)
{
    extern __shared__ __align__(16) __half smem[];
    const uint32_t sbase = smem_u32(smem);

    const int tid   = threadIdx.x;
    const int wid   = tid >> 5;
    const int lane  = tid & 31;
    const int warpM = wid >> 2;          // 0..1
    const int warpN = wid & 3;           // 0..3
    const int rowBase = blockIdx.y * 128;
    const int colBase = blockIdx.x * 128;

    const int nIter = K >> 6;            // K/64 chunks

    float acc[4][4][4];
#pragma unroll
    for (int i = 0; i < 4; i++)
#pragma unroll
        for (int j = 0; j < 4; j++)
#pragma unroll
            for (int r = 0; r < 4; r++) acc[i][j][r] = 0.f;

    const int ldr  = tid >> 3;           // 0..31
    const int ldc8 = (tid & 7) * 8;      // 0..56 step 8

#define LOAD_STAGE(j, s)                                                        \
    do {                                                                        \
        int _kOff = (j) << 6;                                                   \
        uint32_t _sA = sbase + (uint32_t)(s) * (STG_H * 2);                     \
        uint32_t _sB = _sA + 128 * BKH * 2;                                     \
        _Pragma("unroll")                                                       \
        for (int _i = 0; _i < 4; _i++) {                                        \
            int _r = ldr + _i * 32;                                             \
            CP_ASYNC16(_sA + (_r * BKH + ldc8) * 2,                             \
                       A + (size_t)(rowBase + _r) * K + _kOff + ldc8);          \
        }                                                                       \
        _Pragma("unroll")                                                       \
        for (int _i = 0; _i < 4; _i++) {                                        \
            int _r = ldr + _i * 32;                                             \
            CP_ASYNC16(_sB + (_r * BKH + ldc8) * 2,                             \
                       B + (size_t)(colBase + _r) * K + _kOff + ldc8);          \
        }                                                                       \
        CP_COMMIT();                                                            \
    } while (0)

    LOAD_STAGE(0, 0);
    LOAD_STAGE(1, 1);

    const int aRow = (lane & 15);
    const int aKof = (lane >> 4) * 8;
    const int bNof = ((lane >> 4) & 1) * 8 + (lane & 7);
    const int bKof = ((lane >> 3) & 1) * 8;

    int s = 0;
    for (int it = 0; it < nIter; it++) {
        CP_WAIT1();
        __syncthreads();
        // stage (s+2)%3 was computed in iteration it-1; barrier above protects it.
        int jn = it + 2;
        if (jn < nIter) {
            int sn = s + 2; if (sn >= NSTAGE) sn -= NSTAGE;
            LOAD_STAGE(jn, sn);
        } else {
            CP_COMMIT();     // keep group accounting aligned with CP_WAIT1
        }

        uint32_t aBase = sbase + (uint32_t)s * (STG_H * 2) +
                         (warpM * 64) * (BKH * 2);
        uint32_t bBase = sbase + (uint32_t)s * (STG_H * 2) + 128 * BKH * 2 +
                         (warpN * 32) * (BKH * 2);

#pragma unroll
        for (int kk = 0; kk < 4; kk++) {
            uint32_t a[4][4];
            uint32_t b[2][4];
#pragma unroll
            for (int mi = 0; mi < 4; mi++) {
                uint32_t ad = aBase + ((mi * 16 + aRow) * BKH + kk * 16 + aKof) * 2;
                LDMX4(a[mi][0], a[mi][1], a[mi][2], a[mi][3], ad);
            }
#pragma unroll
            for (int nb = 0; nb < 2; nb++) {
                uint32_t bd = bBase + ((nb * 16 + bNof) * BKH + kk * 16 + bKof) * 2;
                LDMX4(b[nb][0], b[nb][1], b[nb][2], b[nb][3], bd);
            }
#pragma unroll
            for (int mi = 0; mi < 4; mi++) {
#pragma unroll
                for (int ni = 0; ni < 4; ni++) {
                    int nb = ni >> 1;
                    int hi = (ni & 1) * 2;
                    MMA16816(acc[mi][ni][0], acc[mi][ni][1],
                             acc[mi][ni][2], acc[mi][ni][3],
                             a[mi][0], a[mi][1], a[mi][2], a[mi][3],
                             b[nb][hi], b[nb][hi + 1]);
                }
            }
        }
        if (++s == NSTAGE) s = 0;
    }
    CP_WAIT0();

    const int erow = rowBase + warpM * 64 + (lane >> 2);
    const int ecol = colBase + warpN * 32 + (lane & 3) * 2;
#pragma unroll
    for (int mi = 0; mi < 4; mi++) {
#pragma unroll
        for (int ni = 0; ni < 4; ni++) {
            float* p0 = C + (size_t)(erow + mi * 16) * ldc + ecol + ni * 8;
            float* p1 = p0 + 8 * (size_t)ldc;
            *reinterpret_cast<float2*>(p0) = make_float2(acc[mi][ni][0], acc[mi][ni][1]);
            *reinterpret_cast<float2*>(p1) = make_float2(acc[mi][ni][2], acc[mi][ni][3]);
        }
    }
}

// ---------------------------------------------------------------------------
// Prep kernels
// A-side buffers get [hi | lo] fp16 split; B-side get [hi | hi] duplicate.
// ---------------------------------------------------------------------------
// x [rows, C] fp32 -> out [rows, 2C]: hi at col c, lo at col C+c
__global__ void split_rows2_kernel(const float* __restrict__ x,
                                   __half* __restrict__ out,
                                   size_t total, int C)
{
    for (size_t i = (size_t)blockIdx.x * blockDim.x + threadIdx.x; i < total;
         i += (size_t)gridDim.x * blockDim.x) {
        size_t r = i / C;
        int    c = (int)(i - r * C);
        float v = x[i];
        __half h = __float2half(v);
        out[r * (2 * (size_t)C) + c]     = h;
        out[r * (2 * (size_t)C) + C + c] = __float2half(v - __half2float(h));
    }
}

// in [R, C] fp32 -> out [C, 2R]: fp16(v) duplicated at (c, r) and (c, R+r)
__global__ void transpose_split2_kernel(const float* __restrict__ in,
                                        __half* __restrict__ out,
                                        int R, int C)
{
    __shared__ float t[32][33];
    int c0 = blockIdx.x * 32, r0 = blockIdx.y * 32;
    int x = threadIdx.x, y = threadIdx.y;
#pragma unroll
    for (int i = 0; i < 32; i += 8)
        t[y + i][x] = in[(size_t)(r0 + y + i) * C + c0 + x];
    __syncthreads();
#pragma unroll
    for (int i = 0; i < 32; i += 8) {
        float v = t[x][y + i];
        __half h = __float2half(v);
        size_t base = (size_t)(c0 + y + i) * (2 * R) + r0 + x;
        out[base]     = h;
        out[base + R] = h;
    }
}

// pack Wfa[HID,64] | Wga[HID,64] | Wb[HID,32] -> W' [256, 2*HID] hi|hi
__global__ void pack_small_kernel(const float* __restrict__ Wfa,
                                  const float* __restrict__ Wga,
                                  const float* __restrict__ Wb,
                                  __half* __restrict__ out)
{
    size_t total = (size_t)256 * HIDD;
    for (size_t i = (size_t)blockIdx.x * blockDim.x + threadIdx.x; i < total;
         i += (size_t)gridDim.x * blockDim.x) {
        int n = (int)(i / HIDD);
        int k = (int)(i % HIDD);
        float v = 0.f;
        if (n < 64)       v = Wfa[(size_t)k * 64 + n];
        else if (n < 128) v = Wga[(size_t)k * 64 + (n - 64)];
        else if (n < 160) v = Wb[(size_t)k * 32 + (n - 128)];
        __half h = __float2half(v);
        size_t base = (size_t)n * K1 + k;
        out[base]        = h;
        out[base + HIDD] = h;
    }
}

// block-diagonal expansion weights: W' [NGE, 256] hi|hi
// rows 0..2047: Wfb^T in cols 0..63 ; rows 2048..4095: Wgb^T in cols 64..127
__global__ void pack_ge_kernel(const float* __restrict__ Wfb,
                               const float* __restrict__ Wgb,
                               __half* __restrict__ out)
{
    size_t total = (size_t)NGE * 128;
    for (size_t i = (size_t)blockIdx.x * blockDim.x + threadIdx.x; i < total;
         i += (size_t)gridDim.x * blockDim.x) {
        int n = (int)(i >> 7);
        int k = (int)(i & 127);
        float v = 0.f;
        if (n < 2048) {
            if (k < 64) v = Wfb[(size_t)k * PP + n];
        } else {
            if (k >= 64) v = Wgb[(size_t)(k - 64) * PP + (n - 2048)];
        }
        __half h = __float2half(v);
        size_t base = (size_t)n * K2 + k;
        out[base]       = h;
        out[base + 128] = h;
    }
}

// extract fa|ga (fp16 hi|lo, [T,256]) + beta from combined GEMM out
__global__ void extract_small_kernel(const float* __restrict__ xc,
                                     __half* __restrict__ ags,
                                     float* __restrict__ bl)
{
    size_t total = (size_t)TT * 160;
    for (size_t i = (size_t)blockIdx.x * blockDim.x + threadIdx.x; i < total;
         i += (size_t)gridDim.x * blockDim.x) {
        int m = (int)(i / 160);
        int c = (int)(i % 160);
        float v = xc[(size_t)m * NCMB + 6144 + c];
        if (c < 128) {
            __half h = __float2half(v);
            size_t base = (size_t)m * K2 + c;
            ags[base]       = h;
            ags[base + 128] = __float2half(v - __half2float(h));
        } else {
            bl[(size_t)m * 32 + (c - 128)] = v;
        }
    }
}

// ---------------------------------------------------------------------------
// conv+silu (+l2norm) — x has row stride ldx (combined buffer)
// ---------------------------------------------------------------------------
__global__ void conv_silu_kernel(const float* __restrict__ x, int ldx,
                                 const float* __restrict__ w,
                                 float* __restrict__ y, int mode)
{
    const int t    = blockIdx.x;
    const int h    = blockIdx.y * 8 + (threadIdx.x >> 5);
    const int lane = threadIdx.x & 31;

    float val[2];
    float ss = 0.f;
#pragma unroll
    for (int e = 0; e < 2; e++) {
        int d = lane + e * 32;
        int p = h * DD + d;
        const float* xp = x + p;
        float w0 = w[p * 4 + 0], w1 = w[p * 4 + 1];
        float w2 = w[p * 4 + 2], w3 = w[p * 4 + 3];
        float acc = xp[(size_t)t * ldx] * w3;
        if (t >= 1) acc = fmaf(xp[(size_t)(t - 1) * ldx], w2, acc);
        if (t >= 2) acc = fmaf(xp[(size_t)(t - 2) * ldx], w1, acc);
        if (t >= 3) acc = fmaf(xp[(size_t)(t - 3) * ldx], w0, acc);
        float sv = acc / (1.f + __expf(-acc));
        val[e] = sv;
        ss += sv * sv;
    }
    if (mode > 0) {
        ss += __shfl_xor_sync(0xffffffffu, ss, 16);
        ss += __shfl_xor_sync(0xffffffffu, ss, 8);
        ss += __shfl_xor_sync(0xffffffffu, ss, 4);
        ss += __shfl_xor_sync(0xffffffffu, ss, 2);
        ss += __shfl_xor_sync(0xffffffffu, ss, 1);
        float r = rsqrtf(ss + 1e-6f);
        if (mode == 2) r *= 0.125f;
        val[0] *= r; val[1] *= r;
    }
    size_t base = (size_t)t * PP + h * DD;
    y[base + lane]      = val[0];
    y[base + lane + 32] = val[1];
}

// decay on gl view inside d_ge (cols 0..2047, row stride NGE), in place
__global__ void decay_kernel(float* __restrict__ ge,
                             const float* __restrict__ dtb,
                             const float* __restrict__ Alog)
{
    const size_t total = (size_t)TT * PP;
    for (size_t idx = (size_t)blockIdx.x * blockDim.x + threadIdx.x;
         idx < total; idx += (size_t)gridDim.x * blockDim.x) {
        int pr  = (int)(idx & (PP - 1));
        size_t row = idx >> 11;
        int h   = pr >> 6;
        size_t a = row * NGE + pr;
        float xv = ge[a] + dtb[pr];
        float sp = (xv > 20.f) ? xv : log1pf(expf(xv));
        ge[a] = expf(-expf(Alog[h]) * sp);
    }
}

__device__ __forceinline__ float kda_step(float S[16],
                                          const float eg[16], const float kk[16],
                                          const float qq[16], float vv, float braw)
{
    float vp0 = 0.f, vp1 = 0.f, vp2 = 0.f, vp3 = 0.f;
#pragma unroll
    for (int j = 0; j < 16; j += 4) {
        float s0 = S[j + 0] * eg[j + 0]; S[j + 0] = s0; vp0 = fmaf(kk[j + 0], s0, vp0);
        float s1 = S[j + 1] * eg[j + 1]; S[j + 1] = s1; vp1 = fmaf(kk[j + 1], s1, vp1);
        float s2 = S[j + 2] * eg[j + 2]; S[j + 2] = s2; vp2 = fmaf(kk[j + 2], s2, vp2);
        float s3 = S[j + 3] * eg[j + 3]; S[j + 3] = s3; vp3 = fmaf(kk[j + 3], s3, vp3);
    }
    float vpred = (vp0 + vp1) + (vp2 + vp3);
    vpred += __shfl_xor_sync(0xffffffffu, vpred, 8);
    vpred += __shfl_xor_sync(0xffffffffu, vpred, 16);
    float b = 1.f / (1.f + __expf(-braw));
    float delta = (vv - vpred) * b;
    float o0 = 0.f, o1 = 0.f, o2 = 0.f, o3 = 0.f;
#pragma unroll
    for (int j = 0; j < 16; j += 4) {
        S[j + 0] = fmaf(kk[j + 0], delta, S[j + 0]); o0 = fmaf(qq[j + 0], S[j + 0], o0);
        S[j + 1] = fmaf(kk[j + 1], delta, S[j + 1]); o1 = fmaf(qq[j + 1], S[j + 1], o1);
        S[j + 2] = fmaf(kk[j + 2], delta, S[j + 2]); o2 = fmaf(qq[j + 2], S[j + 2], o2);
        S[j + 3] = fmaf(kk[j + 3], delta, S[j + 3]); o3 = fmaf(qq[j + 3], S[j + 3], o3);
    }
    float ov = (o0 + o1) + (o2 + o3);
    ov += __shfl_xor_sync(0xffffffffu, ov, 8);
    ov += __shfl_xor_sync(0xffffffffu, ov, 16);
    return ov;
}

// egg has row stride NGE (view into combined buffer); q/k/v stride PP
__global__ void __launch_bounds__(256, 1)
kda_scan_kernel(const float* __restrict__ qg, const float* __restrict__ kg,
                const float* __restrict__ vg, const float* __restrict__ egg,
                const float* __restrict__ bg, float* __restrict__ og)
{
    const int h       = blockIdx.x;
    const int warp    = threadIdx.x >> 5;
    const int lane    = threadIdx.x & 31;
    const int quarter = lane >> 3;
    const int col     = (warp << 3) + (lane & 7);
    const int kb      = quarter << 4;

    const float* ep  = egg + h * DD + kb;
    const float* kp  = kg  + h * DD + kb;
    const float* qp  = qg  + h * DD + kb;
    const float* vpt = vg  + h * DD + col;
    const float* bpt = bg  + h;

    float S[16];
#pragma unroll
    for (int j = 0; j < 16; j++) S[j] = 0.f;

    const float* pf = nullptr;
    size_t pfstride = 0;
    if (warp == 0 && lane < 9) {
        if (lane < 8) {
            const float* bases[4] = {egg, kg, qg, vg};
            const size_t strides[4] = {NGE, PP, PP, PP};
            pf = bases[lane >> 1] + h * DD + (lane & 1) * 32;
            pfstride = strides[lane >> 1];
        } else {
            pf = bg + h;
            pfstride = HH;
        }
    }

    float ea[16], ka[16], qa[16], va, ba;
    float eb[16], kbf[16], qb[16], vb, bb;

#define LOADSTAGE(E, KA, QA, V, B, t)                                            \
    do {                                                                         \
        size_t offe = (size_t)(t) * NGE;                                         \
        size_t off  = (size_t)(t) * PP;                                          \
        _Pragma("unroll")                                                        \
        for (int j = 0; j < 16; j += 4) {                                        \
            *reinterpret_cast<float4*>(&E[j])  =                                 \
                *reinterpret_cast<const float4*>(ep + offe + j);                 \
            *reinterpret_cast<float4*>(&KA[j]) =                                 \
                *reinterpret_cast<const float4*>(kp + off + j);                  \
            *reinterpret_cast<float4*>(&QA[j]) =                                 \
                *reinterpret_cast<const float4*>(qp + off + j);                  \
        }                                                                        \
        V = vpt[off];                                                            \
        B = bpt[(size_t)(t) * HH];                                               \
    } while (0)

    LOADSTAGE(ea, ka, qa, va, ba, 0);
    LOADSTAGE(eb, kbf, qb, vb, bb, 1);

    for (int t = 0; t < TT; t += 2) {
        if (pf) {
            int tp = t + 8;
            if (tp + 1 < TT) {
                const float* p0 = pf + (size_t)tp * pfstride;
                const float* p1 = pf + (size_t)(tp + 1) * pfstride;
                asm volatile("prefetch.global.L2 [%0];" :: "l"(p0));
                asm volatile("prefetch.global.L2 [%0];" :: "l"(p1));
            }
        }
        float ov = kda_step(S, ea, ka, qa, va, ba);
        if (quarter == 0) og[(size_t)t * PP + h * DD + col] = ov;
        if (t + 2 < TT) LOADSTAGE(ea, ka, qa, va, ba, t + 2);

        ov = kda_step(S, eb, kbf, qb, vb, bb);
        if (quarter == 0) og[(size_t)(t + 1) * PP + h * DD + col] = ov;
        if (t + 3 < TT) LOADSTAGE(eb, kbf, qb, vb, bb, t + 3);
    }
#undef LOADSTAGE
}

// gated RMSNorm fused with fp16 hi|lo split ([T, 2*PP]); g2 strided (ld = NGE)
__global__ void rms_gate_split_kernel(const float* __restrict__ o,
                                      const float* __restrict__ g2, int ldg,
                                      const float* __restrict__ wn,
                                      __half* __restrict__ os)
{
    const int t    = blockIdx.x;
    const int h    = blockIdx.y * 8 + (threadIdx.x >> 5);
    const int lane = threadIdx.x & 31;
    size_t base  = (size_t)t * PP + h * DD;
    size_t gbase = (size_t)t * ldg + h * DD;
    size_t obase = (size_t)t * K3 + h * DD;

    float a = o[base + lane];
    float b = o[base + lane + 32];
    float ss = a * a + b * b;
    ss += __shfl_xor_sync(0xffffffffu, ss, 16);
    ss += __shfl_xor_sync(0xffffffffu, ss, 8);
    ss += __shfl_xor_sync(0xffffffffu, ss, 4);
    ss += __shfl_xor_sync(0xffffffffu, ss, 2);
    ss += __shfl_xor_sync(0xffffffffu, ss, 1);
    float r = rsqrtf(ss * (1.f / 64.f) + 1e-5f);

    float ga = g2[gbase + lane];
    float gb = g2[gbase + lane + 32];
    float va = a * r * wn[lane]      * (1.f / (1.f + __expf(-ga)));
    float vb = b * r * wn[lane + 32] * (1.f / (1.f + __expf(-gb)));

    __half ha = __float2half(va);
    __half hb = __float2half(vb);
    os[obase + lane]           = ha;
    os[obase + lane + 32]      = hb;
    os[obase + PP + lane]      = __float2half(va - __half2float(ha));
    os[obase + PP + lane + 32] = __float2half(vb - __half2float(hb));
}

// ---------------------------------------------------------------------------
// Host launcher
// ---------------------------------------------------------------------------
extern "C" void kernel_launch(void* const* d_in, const int* in_sizes, int n_in,
                              void* d_out, int out_size)
{
    const float* x    = (const float*)d_in[0];
    const float* Wq   = (const float*)d_in[1];
    const float* Wk   = (const float*)d_in[2];
    const float* Wv   = (const float*)d_in[3];
    const float* Wb   = (const float*)d_in[4];
    const float* Wfa  = (const float*)d_in[5];
    const float* Wfb  = (const float*)d_in[6];
    const float* dtb  = (const float*)d_in[7];
    const float* Alog = (const float*)d_in[8];
    const float* Wga  = (const float*)d_in[9];
    const float* Wgb  = (const float*)d_in[10];
    const float* cq   = (const float*)d_in[11];
    const float* ck   = (const float*)d_in[12];
    const float* cv   = (const float*)d_in[13];
    const float* wno  = (const float*)d_in[14];
    const float* Wo   = (const float*)d_in[15];
    float* out = (float*)d_out;

    static float *pxc = nullptr, *pge, *pq, *pk, *pv, *pbl;
    static __half *pxs, *pwcs, *pwos, *pos, *pags, *pwges;
    if (!pxc) {
        cudaGetSymbolAddress((void**)&pxc, d_xc);
        cudaGetSymbolAddress((void**)&pge, d_ge);
        cudaGetSymbolAddress((void**)&pq,  d_q);
        cudaGetSymbolAddress((void**)&pk,  d_k);
        cudaGetSymbolAddress((void**)&pv,  d_v);
        cudaGetSymbolAddress((void**)&pbl, d_bl);
        cudaGetSymbolAddress((void**)&pxs,  d_xs);
        cudaGetSymbolAddress((void**)&pwcs, d_wcs);
        cudaGetSymbolAddress((void**)&pwos, d_wos);
        cudaGetSymbolAddress((void**)&pos,  d_os);
        cudaGetSymbolAddress((void**)&pags, d_ags);
        cudaGetSymbolAddress((void**)&pwges, d_wges);
        cudaFuncSetAttribute(mma_gemm_kernel,
                             cudaFuncAttributeMaxDynamicSharedMemorySize,
                             NSTAGE * STG_H * 2);
    }

    dim3 blk(256);
    const size_t smemMMA = NSTAGE * STG_H * 2;   // 110592 B

    // ---- prep: fp16 doubled-K buffers ----
    split_rows2_kernel<<<2048, 256>>>(x, pxs, (size_t)TT * HIDD, HIDD);
    // combined W' rows: Wq^T | Wk^T | Wv^T | small ; row length K1 = 2*HIDD
    transpose_split2_kernel<<<dim3(PP / 32, HIDD / 32), dim3(32, 8)>>>(
        Wq, pwcs + (size_t)0 * K1, HIDD, PP);
    transpose_split2_kernel<<<dim3(PP / 32, HIDD / 32), dim3(32, 8)>>>(
        Wk, pwcs + (size_t)2048 * K1, HIDD, PP);
    transpose_split2_kernel<<<dim3(PP / 32, HIDD / 32), dim3(32, 8)>>>(
        Wv, pwcs + (size_t)4096 * K1, HIDD, PP);
    pack_small_kernel<<<1024, 256>>>(Wfa, Wga, Wb, pwcs + (size_t)6144 * K1);
    transpose_split2_kernel<<<dim3(HIDD / 32, PP / 32), dim3(32, 8)>>>(
        Wo, pwos, PP, HIDD);
    pack_ge_kernel<<<512, 256>>>(Wfb, Wgb, pwges);

    // ---- ONE combined projection GEMM: [T, 8192] @ [8192, 6400] ----
    mma_gemm_kernel<<<dim3(NCMB / 128, TT / 128), blk, smemMMA>>>(
        pxs, pwcs, pxc, K1, NCMB);

    extract_small_kernel<<<1024, 256>>>(pxc, pags, pbl);

    // ---- combined gl|g2 expansion GEMM: [T,256] @ [256, 4096] ----
    mma_gemm_kernel<<<dim3(NGE / 128, TT / 128), blk, smemMMA>>>(
        pags, pwges, pge, K2, NGE);

    // ---- elementwise / scan ----
    decay_kernel<<<4096, 256>>>(pge, dtb, Alog);
    dim3 cgrid(TT, HH / 8);
    conv_silu_kernel<<<cgrid, blk>>>(pxc + 0,    NCMB, cq, pq, 2);
    conv_silu_kernel<<<cgrid, blk>>>(pxc + 2048, NCMB, ck, pk, 1);
    conv_silu_kernel<<<cgrid, blk>>>(pxc + 4096, NCMB, cv, pv, 0);
    kda_scan_kernel<<<HH, 256>>>(pq, pk, pv, pge, pbl, pq /* reuse as o */);
    rms_gate_split_kernel<<<cgrid, blk>>>(pq, pge + 2048, NGE, wno, pos);

    // ---- output projection on tensor cores ----
    mma_gemm_kernel<<<dim3(HIDD / 128, TT / 128), blk, smemMMA>>>(
        pos, pwos, out, K3, HIDD);

    (void)in_sizes; (void)n_in; (void)out_size;
}

// round 11
// speedup vs baseline: 3.8811x; 1.2675x over previous
#include <cuda_runtime.h>
#include <cuda_fp16.h>
#include <cstdint>

// ---------------------------------------------------------------------------
// Problem constants
// ---------------------------------------------------------------------------
#define TT   4096
#define HIDD 4096
#define HH   32
#define DD   64
#define PP   2048
#define NCMB 6400        // combined QKV+small output columns: 3*2048 + 256
#define NGE  4096        // combined gl|g2 expansion columns
#define KGE  128         // ge expansion K

// ---------------------------------------------------------------------------
// Device scratch
// ---------------------------------------------------------------------------
__device__ float d_xc[TT * NCMB];        // combined qkv|small projection out
__device__ float d_ge[TT * NGE];         // combined gl|g2 expansion out
__device__ float d_q [TT * PP];
__device__ float d_k [TT * PP];
__device__ float d_v [TT * PP];
__device__ float d_bl[TT * HH];

__device__ __half d_xs  [(size_t)TT * HIDD];    // A: x fp16
__device__ __half d_wcs [(size_t)NCMB * HIDD];  // B: combined W^T fp16
__device__ __half d_wos [(size_t)HIDD * PP];    // B: Wo^T fp16
__device__ __half d_os  [(size_t)TT * PP];      // A: gated o fp16
__device__ __half d_ags [(size_t)TT * KGE];     // A: [fa|ga] fp16
__device__ __half d_wges[(size_t)NGE * KGE];    // B: blockdiag exp W^T fp16

// ---------------------------------------------------------------------------
// cp.async / ldmatrix / mma helpers
// ---------------------------------------------------------------------------
__device__ __forceinline__ uint32_t smem_u32(const void* p) {
    uint32_t a;
    asm("{ .reg .u64 t; cvta.to.shared.u64 t, %1; cvt.u32.u64 %0, t; }"
        : "=r"(a) : "l"(p));
    return a;
}
#define CP_ASYNC16(smem, gptr) \
    asm volatile("cp.async.cg.shared.global [%0], [%1], 16;\n" \
                 :: "r"(smem), "l"(gptr))
#define CP_COMMIT() asm volatile("cp.async.commit_group;\n" ::: "memory")
#define CP_WAIT1()  asm volatile("cp.async.wait_group 1;\n" ::: "memory")
#define CP_WAIT0()  asm volatile("cp.async.wait_group 0;\n" ::: "memory")

#define LDMX4(r0, r1, r2, r3, addr)                                       \
    asm volatile("ldmatrix.sync.aligned.m8n8.x4.shared.b16 "              \
                 "{%0, %1, %2, %3}, [%4];"                                \
                 : "=r"(r0), "=r"(r1), "=r"(r2), "=r"(r3) : "r"(addr))

#define MMA16816(c0, c1, c2, c3, a0, a1, a2, a3, b0, b1)                  \
    asm volatile("mma.sync.aligned.m16n8k16.row.col.f32.f16.f16.f32 "     \
                 "{%0, %1, %2, %3}, {%4, %5, %6, %7}, {%8, %9}, "         \
                 "{%0, %1, %2, %3};"                                      \
                 : "+f"(c0), "+f"(c1), "+f"(c2), "+f"(c3)                 \
                 : "r"(a0), "r"(a1), "r"(a2), "r"(a3), "r"(b0), "r"(b1))

// ---------------------------------------------------------------------------
// fp16 HMMA GEMM:  C = A @ B^T  (fp32 accum/out)
// A: [M,K] fp16 row-major.  B: [N,K] fp16 row-major.
// Block 128x128, BK=64, 8 warps (2x4), warp tile 64x32.
// 3-stage cp.async pipeline, ONE __syncthreads per 64-wide K-chunk.
// ---------------------------------------------------------------------------
#define BKH     72                      // 64 halves + 8 pad (144 B rows)
#define STG_H   (2 * 128 * BKH)         // halves per stage (A then B)
#define NSTAGE  3

__global__ void __launch_bounds__(256, 2)
mma_gemm_kernel(const __half* __restrict__ A,
                const __half* __restrict__ B,
                float* __restrict__ C, int K, int ldc)
{
    extern __shared__ __align__(16) __half smem[];
    const uint32_t sbase = smem_u32(smem);

    const int tid   = threadIdx.x;
    const int wid   = tid >> 5;
    const int lane  = tid & 31;
    const int warpM = wid >> 2;          // 0..1
    const int warpN = wid & 3;           // 0..3
    const int rowBase = blockIdx.y * 128;
    const int colBase = blockIdx.x * 128;

    const int nIter = K >> 6;            // K/64 chunks

    float acc[4][4][4];
#pragma unroll
    for (int i = 0; i < 4; i++)
#pragma unroll
        for (int j = 0; j < 4; j++)
#pragma unroll
            for (int r = 0; r < 4; r++) acc[i][j][r] = 0.f;

    const int ldr  = tid >> 3;           // 0..31
    const int ldc8 = (tid & 7) * 8;      // 0..56 step 8

#define LOAD_STAGE(j, s)                                                        \
    do {                                                                        \
        int _kOff = (j) << 6;                                                   \
        uint32_t _sA = sbase + (uint32_t)(s) * (STG_H * 2);                     \
        uint32_t _sB = _sA + 128 * BKH * 2;                                     \
        _Pragma("unroll")                                                       \
        for (int _i = 0; _i < 4; _i++) {                                        \
            int _r = ldr + _i * 32;                                             \
            CP_ASYNC16(_sA + (_r * BKH + ldc8) * 2,                             \
                       A + (size_t)(rowBase + _r) * K + _kOff + ldc8);          \
        }                                                                       \
        _Pragma("unroll")                                                       \
        for (int _i = 0; _i < 4; _i++) {                                        \
            int _r = ldr + _i * 32;                                             \
            CP_ASYNC16(_sB + (_r * BKH + ldc8) * 2,                             \
                       B + (size_t)(colBase + _r) * K + _kOff + ldc8);          \
        }                                                                       \
        CP_COMMIT();                                                            \
    } while (0)

    LOAD_STAGE(0, 0);
    if (nIter > 1) LOAD_STAGE(1, 1); else CP_COMMIT();

    const int aRow = (lane & 15);
    const int aKof = (lane >> 4) * 8;
    const int bNof = ((lane >> 4) & 1) * 8 + (lane & 7);
    const int bKof = ((lane >> 3) & 1) * 8;

    int s = 0;
    for (int it = 0; it < nIter; it++) {
        CP_WAIT1();
        __syncthreads();
        // stage (s+2)%3 was computed in iteration it-1; barrier above protects it.
        int jn = it + 2;
        if (jn < nIter) {
            int sn = s + 2; if (sn >= NSTAGE) sn -= NSTAGE;
            LOAD_STAGE(jn, sn);
        } else {
            CP_COMMIT();     // keep group accounting aligned with CP_WAIT1
        }

        uint32_t aBase = sbase + (uint32_t)s * (STG_H * 2) +
                         (warpM * 64) * (BKH * 2);
        uint32_t bBase = sbase + (uint32_t)s * (STG_H * 2) + 128 * BKH * 2 +
                         (warpN * 32) * (BKH * 2);

#pragma unroll
        for (int kk = 0; kk < 4; kk++) {
            uint32_t a[4][4];
            uint32_t b[2][4];
#pragma unroll
            for (int mi = 0; mi < 4; mi++) {
                uint32_t ad = aBase + ((mi * 16 + aRow) * BKH + kk * 16 + aKof) * 2;
                LDMX4(a[mi][0], a[mi][1], a[mi][2], a[mi][3], ad);
            }
#pragma unroll
            for (int nb = 0; nb < 2; nb++) {
                uint32_t bd = bBase + ((nb * 16 + bNof) * BKH + kk * 16 + bKof) * 2;
                LDMX4(b[nb][0], b[nb][1], b[nb][2], b[nb][3], bd);
            }
#pragma unroll
            for (int mi = 0; mi < 4; mi++) {
#pragma unroll
                for (int ni = 0; ni < 4; ni++) {
                    int nb = ni >> 1;
                    int hi = (ni & 1) * 2;
                    MMA16816(acc[mi][ni][0], acc[mi][ni][1],
                             acc[mi][ni][2], acc[mi][ni][3],
                             a[mi][0], a[mi][1], a[mi][2], a[mi][3],
                             b[nb][hi], b[nb][hi + 1]);
                }
            }
        }
        if (++s == NSTAGE) s = 0;
    }
    CP_WAIT0();

    const int erow = rowBase + warpM * 64 + (lane >> 2);
    const int ecol = colBase + warpN * 32 + (lane & 3) * 2;
#pragma unroll
    for (int mi = 0; mi < 4; mi++) {
#pragma unroll
        for (int ni = 0; ni < 4; ni++) {
            float* p0 = C + (size_t)(erow + mi * 16) * ldc + ecol + ni * 8;
            float* p1 = p0 + 8 * (size_t)ldc;
            *reinterpret_cast<float2*>(p0) = make_float2(acc[mi][ni][0], acc[mi][ni][1]);
            *reinterpret_cast<float2*>(p1) = make_float2(acc[mi][ni][2], acc[mi][ni][3]);
        }
    }
}

// ---------------------------------------------------------------------------
// Prep kernels — plain fp16 conversion
// ---------------------------------------------------------------------------
__global__ void convert_fp16_kernel(const float* __restrict__ x,
                                    __half* __restrict__ out, size_t n)
{
    for (size_t i = (size_t)blockIdx.x * blockDim.x + threadIdx.x; i < n;
         i += (size_t)gridDim.x * blockDim.x) {
        out[i] = __float2half(x[i]);
    }
}

// in [R, C] fp32 -> out [C, R] fp16
__global__ void transpose_h_kernel(const float* __restrict__ in,
                                   __half* __restrict__ out,
                                   int R, int C)
{
    __shared__ float t[32][33];
    int c0 = blockIdx.x * 32, r0 = blockIdx.y * 32;
    int x = threadIdx.x, y = threadIdx.y;
#pragma unroll
    for (int i = 0; i < 32; i += 8)
        t[y + i][x] = in[(size_t)(r0 + y + i) * C + c0 + x];
    __syncthreads();
#pragma unroll
    for (int i = 0; i < 32; i += 8) {
        float v = t[x][y + i];
        out[(size_t)(c0 + y + i) * R + r0 + x] = __float2half(v);
    }
}

// pack Wfa[HID,64] | Wga[HID,64] | Wb[HID,32] -> W' [256, HID] fp16
__global__ void pack_small_kernel(const float* __restrict__ Wfa,
                                  const float* __restrict__ Wga,
                                  const float* __restrict__ Wb,
                                  __half* __restrict__ out)
{
    size_t total = (size_t)256 * HIDD;
    for (size_t i = (size_t)blockIdx.x * blockDim.x + threadIdx.x; i < total;
         i += (size_t)gridDim.x * blockDim.x) {
        int n = (int)(i / HIDD);
        int k = (int)(i % HIDD);
        float v = 0.f;
        if (n < 64)       v = Wfa[(size_t)k * 64 + n];
        else if (n < 128) v = Wga[(size_t)k * 64 + (n - 64)];
        else if (n < 160) v = Wb[(size_t)k * 32 + (n - 128)];
        out[i] = __float2half(v);
    }
}

// block-diagonal expansion weights: W' [NGE, 128] fp16
// rows 0..2047: Wfb^T in cols 0..63 ; rows 2048..4095: Wgb^T in cols 64..127
__global__ void pack_ge_kernel(const float* __restrict__ Wfb,
                               const float* __restrict__ Wgb,
                               __half* __restrict__ out)
{
    size_t total = (size_t)NGE * KGE;
    for (size_t i = (size_t)blockIdx.x * blockDim.x + threadIdx.x; i < total;
         i += (size_t)gridDim.x * blockDim.x) {
        int n = (int)(i >> 7);
        int k = (int)(i & 127);
        float v = 0.f;
        if (n < 2048) {
            if (k < 64) v = Wfb[(size_t)k * PP + n];
        } else {
            if (k >= 64) v = Wgb[(size_t)(k - 64) * PP + (n - 2048)];
        }
        out[i] = __float2half(v);
    }
}

// extract fa|ga (fp16 [T,128]) + beta from combined GEMM out
__global__ void extract_small_kernel(const float* __restrict__ xc,
                                     __half* __restrict__ ags,
                                     float* __restrict__ bl)
{
    size_t total = (size_t)TT * 160;
    for (size_t i = (size_t)blockIdx.x * blockDim.x + threadIdx.x; i < total;
         i += (size_t)gridDim.x * blockDim.x) {
        int m = (int)(i / 160);
        int c = (int)(i % 160);
        float v = xc[(size_t)m * NCMB + 6144 + c];
        if (c < 128) {
            ags[(size_t)m * KGE + c] = __float2half(v);
        } else {
            bl[(size_t)m * 32 + (c - 128)] = v;
        }
    }
}

// ---------------------------------------------------------------------------
// conv+silu (+l2norm) — x has row stride ldx (combined buffer)
// ---------------------------------------------------------------------------
__global__ void conv_silu_kernel(const float* __restrict__ x, int ldx,
                                 const float* __restrict__ w,
                                 float* __restrict__ y, int mode)
{
    const int t    = blockIdx.x;
    const int h    = blockIdx.y * 8 + (threadIdx.x >> 5);
    const int lane = threadIdx.x & 31;

    float val[2];
    float ss = 0.f;
#pragma unroll
    for (int e = 0; e < 2; e++) {
        int d = lane + e * 32;
        int p = h * DD + d;
        const float* xp = x + p;
        float w0 = w[p * 4 + 0], w1 = w[p * 4 + 1];
        float w2 = w[p * 4 + 2], w3 = w[p * 4 + 3];
        float acc = xp[(size_t)t * ldx] * w3;
        if (t >= 1) acc = fmaf(xp[(size_t)(t - 1) * ldx], w2, acc);
        if (t >= 2) acc = fmaf(xp[(size_t)(t - 2) * ldx], w1, acc);
        if (t >= 3) acc = fmaf(xp[(size_t)(t - 3) * ldx], w0, acc);
        float sv = acc / (1.f + __expf(-acc));
        val[e] = sv;
        ss += sv * sv;
    }
    if (mode > 0) {
        ss += __shfl_xor_sync(0xffffffffu, ss, 16);
        ss += __shfl_xor_sync(0xffffffffu, ss, 8);
        ss += __shfl_xor_sync(0xffffffffu, ss, 4);
        ss += __shfl_xor_sync(0xffffffffu, ss, 2);
        ss += __shfl_xor_sync(0xffffffffu, ss, 1);
        float r = rsqrtf(ss + 1e-6f);
        if (mode == 2) r *= 0.125f;
        val[0] *= r; val[1] *= r;
    }
    size_t base = (size_t)t * PP + h * DD;
    y[base + lane]      = val[0];
    y[base + lane + 32] = val[1];
}

// decay on gl view inside d_ge (cols 0..2047, row stride NGE), in place
__global__ void decay_kernel(float* __restrict__ ge,
                             const float* __restrict__ dtb,
                             const float* __restrict__ Alog)
{
    const size_t total = (size_t)TT * PP;
    for (size_t idx = (size_t)blockIdx.x * blockDim.x + threadIdx.x;
         idx < total; idx += (size_t)gridDim.x * blockDim.x) {
        int pr  = (int)(idx & (PP - 1));
        size_t row = idx >> 11;
        int h   = pr >> 6;
        size_t a = row * NGE + pr;
        float xv = ge[a] + dtb[pr];
        float sp = (xv > 20.f) ? xv : log1pf(expf(xv));
        ge[a] = expf(-expf(Alog[h]) * sp);
    }
}

__device__ __forceinline__ float kda_step(float S[16],
                                          const float eg[16], const float kk[16],
                                          const float qq[16], float vv, float braw)
{
    float vp0 = 0.f, vp1 = 0.f, vp2 = 0.f, vp3 = 0.f;
#pragma unroll
    for (int j = 0; j < 16; j += 4) {
        float s0 = S[j + 0] * eg[j + 0]; S[j + 0] = s0; vp0 = fmaf(kk[j + 0], s0, vp0);
        float s1 = S[j + 1] * eg[j + 1]; S[j + 1] = s1; vp1 = fmaf(kk[j + 1], s1, vp1);
        float s2 = S[j + 2] * eg[j + 2]; S[j + 2] = s2; vp2 = fmaf(kk[j + 2], s2, vp2);
        float s3 = S[j + 3] * eg[j + 3]; S[j + 3] = s3; vp3 = fmaf(kk[j + 3], s3, vp3);
    }
    float vpred = (vp0 + vp1) + (vp2 + vp3);
    vpred += __shfl_xor_sync(0xffffffffu, vpred, 8);
    vpred += __shfl_xor_sync(0xffffffffu, vpred, 16);
    float b = 1.f / (1.f + __expf(-braw));
    float delta = (vv - vpred) * b;
    float o0 = 0.f, o1 = 0.f, o2 = 0.f, o3 = 0.f;
#pragma unroll
    for (int j = 0; j < 16; j += 4) {
        S[j + 0] = fmaf(kk[j + 0], delta, S[j + 0]); o0 = fmaf(qq[j + 0], S[j + 0], o0);
        S[j + 1] = fmaf(kk[j + 1], delta, S[j + 1]); o1 = fmaf(qq[j + 1], S[j + 1], o1);
        S[j + 2] = fmaf(kk[j + 2], delta, S[j + 2]); o2 = fmaf(qq[j + 2], S[j + 2], o2);
        S[j + 3] = fmaf(kk[j + 3], delta, S[j + 3]); o3 = fmaf(qq[j + 3], S[j + 3], o3);
    }
    float ov = (o0 + o1) + (o2 + o3);
    ov += __shfl_xor_sync(0xffffffffu, ov, 8);
    ov += __shfl_xor_sync(0xffffffffu, ov, 16);
    return ov;
}

// egg has row stride NGE (view into combined buffer); q/k/v stride PP
__global__ void __launch_bounds__(256, 1)
kda_scan_kernel(const float* __restrict__ qg, const float* __restrict__ kg,
                const float* __restrict__ vg, const float* __restrict__ egg,
                const float* __restrict__ bg, float* __restrict__ og)
{
    const int h       = blockIdx.x;
    const int warp    = threadIdx.x >> 5;
    const int lane    = threadIdx.x & 31;
    const int quarter = lane >> 3;
    const int col     = (warp << 3) + (lane & 7);
    const int kb      = quarter << 4;

    const float* ep  = egg + h * DD + kb;
    const float* kp  = kg  + h * DD + kb;
    const float* qp  = qg  + h * DD + kb;
    const float* vpt = vg  + h * DD + col;
    const float* bpt = bg  + h;

    float S[16];
#pragma unroll
    for (int j = 0; j < 16; j++) S[j] = 0.f;

    const float* pf = nullptr;
    size_t pfstride = 0;
    if (warp == 0 && lane < 9) {
        if (lane < 8) {
            const float* bases[4] = {egg, kg, qg, vg};
            const size_t strides[4] = {NGE, PP, PP, PP};
            pf = bases[lane >> 1] + h * DD + (lane & 1) * 32;
            pfstride = strides[lane >> 1];
        } else {
            pf = bg + h;
            pfstride = HH;
        }
    }

    float ea[16], ka[16], qa[16], va, ba;
    float eb[16], kbf[16], qb[16], vb, bb;

#define LOADSTAGE(E, KA, QA, V, B, t)                                            \
    do {                                                                         \
        size_t offe = (size_t)(t) * NGE;                                         \
        size_t off  = (size_t)(t) * PP;                                          \
        _Pragma("unroll")                                                        \
        for (int j = 0; j < 16; j += 4) {                                        \
            *reinterpret_cast<float4*>(&E[j])  =                                 \
                *reinterpret_cast<const float4*>(ep + offe + j);                 \
            *reinterpret_cast<float4*>(&KA[j]) =                                 \
                *reinterpret_cast<const float4*>(kp + off + j);                  \
            *reinterpret_cast<float4*>(&QA[j]) =                                 \
                *reinterpret_cast<const float4*>(qp + off + j);                  \
        }                                                                        \
        V = vpt[off];                                                            \
        B = bpt[(size_t)(t) * HH];                                               \
    } while (0)

    LOADSTAGE(ea, ka, qa, va, ba, 0);
    LOADSTAGE(eb, kbf, qb, vb, bb, 1);

    for (int t = 0; t < TT; t += 2) {
        if (pf) {
            int tp = t + 8;
            if (tp + 1 < TT) {
                const float* p0 = pf + (size_t)tp * pfstride;
                const float* p1 = pf + (size_t)(tp + 1) * pfstride;
                asm volatile("prefetch.global.L2 [%0];" :: "l"(p0));
                asm volatile("prefetch.global.L2 [%0];" :: "l"(p1));
            }
        }
        float ov = kda_step(S, ea, ka, qa, va, ba);
        if (quarter == 0) og[(size_t)t * PP + h * DD + col] = ov;
        if (t + 2 < TT) LOADSTAGE(ea, ka, qa, va, ba, t + 2);

        ov = kda_step(S, eb, kbf, qb, vb, bb);
        if (quarter == 0) og[(size_t)(t + 1) * PP + h * DD + col] = ov;
        if (t + 3 < TT) LOADSTAGE(eb, kbf, qb, vb, bb, t + 3);
    }
#undef LOADSTAGE
}

// gated RMSNorm -> fp16 ([T, PP]); g2 strided (ld = NGE)
__global__ void rms_gate_h_kernel(const float* __restrict__ o,
                                  const float* __restrict__ g2, int ldg,
                                  const float* __restrict__ wn,
                                  __half* __restrict__ os)
{
    const int t    = blockIdx.x;
    const int h    = blockIdx.y * 8 + (threadIdx.x >> 5);
    const int lane = threadIdx.x & 31;
    size_t base  = (size_t)t * PP + h * DD;
    size_t gbase = (size_t)t * ldg + h * DD;

    float a = o[base + lane];
    float b = o[base + lane + 32];
    float ss = a * a + b * b;
    ss += __shfl_xor_sync(0xffffffffu, ss, 16);
    ss += __shfl_xor_sync(0xffffffffu, ss, 8);
    ss += __shfl_xor_sync(0xffffffffu, ss, 4);
    ss += __shfl_xor_sync(0xffffffffu, ss, 2);
    ss += __shfl_xor_sync(0xffffffffu, ss, 1);
    float r = rsqrtf(ss * (1.f / 64.f) + 1e-5f);

    float ga = g2[gbase + lane];
    float gb = g2[gbase + lane + 32];
    float va = a * r * wn[lane]      * (1.f / (1.f + __expf(-ga)));
    float vb = b * r * wn[lane + 32] * (1.f / (1.f + __expf(-gb)));

    os[base + lane]      = __float2half(va);
    os[base + lane + 32] = __float2half(vb);
}

// ---------------------------------------------------------------------------
// Host launcher
// ---------------------------------------------------------------------------
extern "C" void kernel_launch(void* const* d_in, const int* in_sizes, int n_in,
                              void* d_out, int out_size)
{
    const float* x    = (const float*)d_in[0];
    const float* Wq   = (const float*)d_in[1];
    const float* Wk   = (const float*)d_in[2];
    const float* Wv   = (const float*)d_in[3];
    const float* Wb   = (const float*)d_in[4];
    const float* Wfa  = (const float*)d_in[5];
    const float* Wfb  = (const float*)d_in[6];
    const float* dtb  = (const float*)d_in[7];
    const float* Alog = (const float*)d_in[8];
    const float* Wga  = (const float*)d_in[9];
    const float* Wgb  = (const float*)d_in[10];
    const float* cq   = (const float*)d_in[11];
    const float* ck   = (const float*)d_in[12];
    const float* cv   = (const float*)d_in[13];
    const float* wno  = (const float*)d_in[14];
    const float* Wo   = (const float*)d_in[15];
    float* out = (float*)d_out;

    static float *pxc = nullptr, *pge, *pq, *pk, *pv, *pbl;
    static __half *pxs, *pwcs, *pwos, *pos, *pags, *pwges;
    if (!pxc) {
        cudaGetSymbolAddress((void**)&pxc, d_xc);
        cudaGetSymbolAddress((void**)&pge, d_ge);
        cudaGetSymbolAddress((void**)&pq,  d_q);
        cudaGetSymbolAddress((void**)&pk,  d_k);
        cudaGetSymbolAddress((void**)&pv,  d_v);
        cudaGetSymbolAddress((void**)&pbl, d_bl);
        cudaGetSymbolAddress((void**)&pxs,  d_xs);
        cudaGetSymbolAddress((void**)&pwcs, d_wcs);
        cudaGetSymbolAddress((void**)&pwos, d_wos);
        cudaGetSymbolAddress((void**)&pos,  d_os);
        cudaGetSymbolAddress((void**)&pags, d_ags);
        cudaGetSymbolAddress((void**)&pwges, d_wges);
        cudaFuncSetAttribute(mma_gemm_kernel,
                             cudaFuncAttributeMaxDynamicSharedMemorySize,
                             NSTAGE * STG_H * 2);
    }

    dim3 blk(256);
    const size_t smemMMA = NSTAGE * STG_H * 2;   // 110592 B

    // ---- prep: fp16 buffers ----
    convert_fp16_kernel<<<2048, 256>>>(x, pxs, (size_t)TT * HIDD);
    // combined W' rows: Wq^T | Wk^T | Wv^T | small ; row length HIDD
    transpose_h_kernel<<<dim3(PP / 32, HIDD / 32), dim3(32, 8)>>>(
        Wq, pwcs + (size_t)0 * HIDD, HIDD, PP);
    transpose_h_kernel<<<dim3(PP / 32, HIDD / 32), dim3(32, 8)>>>(
        Wk, pwcs + (size_t)2048 * HIDD, HIDD, PP);
    transpose_h_kernel<<<dim3(PP / 32, HIDD / 32), dim3(32, 8)>>>(
        Wv, pwcs + (size_t)4096 * HIDD, HIDD, PP);
    pack_small_kernel<<<1024, 256>>>(Wfa, Wga, Wb, pwcs + (size_t)6144 * HIDD);
    transpose_h_kernel<<<dim3(HIDD / 32, PP / 32), dim3(32, 8)>>>(
        Wo, pwos, PP, HIDD);
    pack_ge_kernel<<<512, 256>>>(Wfb, Wgb, pwges);

    // ---- ONE combined projection GEMM: [T, 4096] @ [4096, 6400] ----
    mma_gemm_kernel<<<dim3(NCMB / 128, TT / 128), blk, smemMMA>>>(
        pxs, pwcs, pxc, HIDD, NCMB);

    extract_small_kernel<<<1024, 256>>>(pxc, pags, pbl);

    // ---- combined gl|g2 expansion GEMM: [T,128] @ [128, 4096] ----
    mma_gemm_kernel<<<dim3(NGE / 128, TT / 128), blk, smemMMA>>>(
        pags, pwges, pge, KGE, NGE);

    // ---- elementwise / scan ----
    decay_kernel<<<4096, 256>>>(pge, dtb, Alog);
    dim3 cgrid(TT, HH / 8);
    conv_silu_kernel<<<cgrid, blk>>>(pxc + 0,    NCMB, cq, pq, 2);
    conv_silu_kernel<<<cgrid, blk>>>(pxc + 2048, NCMB, ck, pk, 1);
    conv_silu_kernel<<<cgrid, blk>>>(pxc + 4096, NCMB, cv, pv, 0);
    kda_scan_kernel<<<HH, 256>>>(pq, pk, pv, pge, pbl, pq /* reuse as o */);
    rms_gate_h_kernel<<<cgrid, blk>>>(pq, pge + 2048, NGE, wno, pos);

    // ---- output projection on tensor cores ----
    mma_gemm_kernel<<<dim3(HIDD / 128, TT / 128), blk, smemMMA>>>(
        pos, pwos, out, PP, HIDD);

    (void)in_sizes; (void)n_in; (void)out_size;
}